// round 2
// baseline (speedup 1.0000x reference)
#include <cuda_runtime.h>
#include <math.h>

// Problem constants
#define BB 256      // batch
#define TT 512      // time steps
#define VV 10       // vocab
#define EE 10       // embed dim
#define HH 1024     // hidden
#define CC 10       // out classes
#define KW 1034     // weight row stride (E + H)

// ---------------- device scratch (no allocations allowed) ----------------
__device__ float g_h[BB * HH];            // hidden state
__device__ float g_z[BB * HH];            // z gate scratch
__device__ float g_hr[BB * HH];           // h * r scratch
__device__ float g_pre[3][VV][HH];        // precomputed x-path per token: [z,r,cand]
__device__ unsigned g_count;              // barrier arrival counter (zero-init)
__device__ volatile unsigned g_phase;     // barrier generation

// ---------------- packed fp32x2 FMA (Blackwell full-rate fp32) -----------
__device__ __forceinline__ float2 ffma2(float2 a, float2 b, float2 c) {
    float2 d;
    asm("fma.rn.f32x2 %0, %1, %2, %3;"
        : "=l"(reinterpret_cast<unsigned long long&>(d))
        : "l"(reinterpret_cast<unsigned long long&>(a)),
          "l"(reinterpret_cast<unsigned long long&>(b)),
          "l"(reinterpret_cast<unsigned long long&>(c)));
    return d;
}

// ---------------- grid-wide barrier (all CTAs resident) ------------------
__device__ __forceinline__ void grid_sync(unsigned nb) {
    __syncthreads();
    if (threadIdx.x == 0) {
        __threadfence();                       // push writes to L2 + IVALL
        unsigned ph = g_phase;
        if (atomicAdd(&g_count, 1u) == nb - 1u) {
            g_count = 0u;
            __threadfence();
            g_phase = ph + 1u;                 // release
        } else {
            while (g_phase == ph) { __nanosleep(64); }
        }
        __threadfence();                       // invalidate stale L1 lines
    }
    __syncthreads();
}

// ---------------- precompute x-path tables -------------------------------
// pre[g][v][j] = sum_e embed[v][e] * Wg[j][H + e]
__global__ void precompute_kernel(const float* __restrict__ embed,
                                  const float* __restrict__ Wz,
                                  const float* __restrict__ Wr,
                                  const float* __restrict__ Wc) {
    int idx = blockIdx.x * blockDim.x + threadIdx.x;
    if (idx >= 3 * VV * HH) return;
    int g = idx / (VV * HH);
    int rem = idx - g * (VV * HH);
    int v = rem / HH;
    int j = rem - v * HH;
    const float* Wg = (g == 0) ? Wz : (g == 1) ? Wr : Wc;
    float s = 0.f;
#pragma unroll
    for (int e = 0; e < EE; ++e)
        s += embed[v * EE + e] * Wg[j * KW + HH + e];
    g_pre[g][v][j] = s;
}

// ---------------- persistent GRU kernel ----------------------------------
__global__ void __launch_bounds__(256)
gru_persistent(const int* __restrict__ x,
               const float* __restrict__ Wz,
               const float* __restrict__ Wr,
               const float* __restrict__ Wc,
               const float* __restrict__ Wph,
               const float* __restrict__ bp,
               float* __restrict__ out,
               int nb) {
    __shared__ float sA[32 * 68];   // [k][m], padded to keep 16B alignment
    __shared__ float sB[32 * 68];   // [k][n]

    const int tid = threadIdx.x;
    const int tx = tid & 15;        // n-dim thread coord (x4)
    const int ty = tid >> 4;        // m-dim thread coord

    // zero hidden state (must happen every launch: globals persist)
    for (int i = blockIdx.x * 256 + tid; i < BB * HH; i += nb * 256)
        g_h[i] = 0.f;
    grid_sync(nb);

    for (int t = 0; t < TT; ++t) {
        // ============ phase 1: z and r gates (M=256, N=2048, K=1024) =====
        // 128 tiles of 64x64; tiles 0..63 -> z (Wz), 64..127 -> r (Wr)
        for (int tile = blockIdx.x; tile < 128; tile += nb) {
            const int mt = tile & 3;        // 4 M tiles
            const int nt = tile >> 2;       // 32 N tiles
            const int gate = nt >> 4;       // 0 = z, 1 = r
            const int jb = (nt & 15) << 6;  // col base within gate
            const int bm = mt << 6;         // row base
            const float* __restrict__ Wg = gate ? Wr : Wz;

            float2 acc[4][2];
#pragma unroll
            for (int i = 0; i < 4; ++i) {
                acc[i][0] = make_float2(0.f, 0.f);
                acc[i][1] = make_float2(0.f, 0.f);
            }

            const int aRow = tid >> 3;          // 0..31
            const int aK = (tid & 7) << 2;      // 0,4,..,28
            const int bRow = tid >> 2;          // 0..63
            const int bC = (tid & 3) << 1;      // 0,2,4,6

            for (int k0 = 0; k0 < HH; k0 += 32) {
                // A tile: h[bm..bm+63][k0..k0+31]  (16B-aligned rows)
                float4 va0 = *reinterpret_cast<const float4*>(&g_h[(bm + aRow) * HH + k0 + aK]);
                float4 va1 = *reinterpret_cast<const float4*>(&g_h[(bm + aRow + 32) * HH + k0 + aK]);
                sA[(aK + 0) * 68 + aRow] = va0.x;
                sA[(aK + 1) * 68 + aRow] = va0.y;
                sA[(aK + 2) * 68 + aRow] = va0.z;
                sA[(aK + 3) * 68 + aRow] = va0.w;
                sA[(aK + 0) * 68 + aRow + 32] = va1.x;
                sA[(aK + 1) * 68 + aRow + 32] = va1.y;
                sA[(aK + 2) * 68 + aRow + 32] = va1.z;
                sA[(aK + 3) * 68 + aRow + 32] = va1.w;
                // B tile: Wg[jb..jb+63][k0..k0+31]  (rows only 8B aligned -> float2)
#pragma unroll
                for (int q = 0; q < 4; ++q) {
                    int kk = bC + q * 8;
                    float2 vb = *reinterpret_cast<const float2*>(&Wg[(jb + bRow) * KW + k0 + kk]);
                    sB[(kk + 0) * 68 + bRow] = vb.x;
                    sB[(kk + 1) * 68 + bRow] = vb.y;
                }
                __syncthreads();
#pragma unroll
                for (int k = 0; k < 32; ++k) {
                    float4 a = *reinterpret_cast<const float4*>(&sA[k * 68 + (ty << 2)]);
                    float4 b = *reinterpret_cast<const float4*>(&sB[k * 68 + (tx << 2)]);
                    float2 b01 = make_float2(b.x, b.y);
                    float2 b23 = make_float2(b.z, b.w);
                    float av[4] = {a.x, a.y, a.z, a.w};
#pragma unroll
                    for (int i = 0; i < 4; ++i) {
                        float2 pa = make_float2(av[i], av[i]);
                        acc[i][0] = ffma2(pa, b01, acc[i][0]);
                        acc[i][1] = ffma2(pa, b23, acc[i][1]);
                    }
                }
                __syncthreads();
            }
            // epilogue: sigmoid + store z / hr
#pragma unroll
            for (int i = 0; i < 4; ++i) {
                const int b = bm + (ty << 2) + i;
                const int tok = x[b * TT + t];
                const int jcol = jb + (tx << 2);
                const float* pre = &g_pre[gate][tok][jcol];
                float vv[4] = {acc[i][0].x, acc[i][0].y, acc[i][1].x, acc[i][1].y};
#pragma unroll
                for (int n = 0; n < 4; ++n) {
                    float v = vv[n] + pre[n];
                    float s = 1.f / (1.f + expf(-v));
                    int idx = b * HH + jcol + n;
                    if (gate == 0) g_z[idx] = s;
                    else           g_hr[idx] = s * g_h[idx];
                }
            }
        }
        grid_sync(nb);

        // ============ phase 2: candidate + state update (M=256, N=1024) ==
        // 128 tiles of 32x64
        for (int tile = blockIdx.x; tile < 128; tile += nb) {
            const int mt = tile & 7;        // 8 M tiles of 32
            const int nt = tile >> 3;       // 16 N tiles of 64
            const int bm = mt << 5;
            const int jb = nt << 6;

            float2 acc[2][2];
#pragma unroll
            for (int i = 0; i < 2; ++i) {
                acc[i][0] = make_float2(0.f, 0.f);
                acc[i][1] = make_float2(0.f, 0.f);
            }

            const int aRow = tid >> 3;      // 0..31
            const int aK = (tid & 7) << 2;
            const int bRow = tid >> 2;      // 0..63
            const int bC = (tid & 3) << 1;

            for (int k0 = 0; k0 < HH; k0 += 32) {
                float4 va = *reinterpret_cast<const float4*>(&g_hr[(bm + aRow) * HH + k0 + aK]);
                sA[(aK + 0) * 68 + aRow] = va.x;
                sA[(aK + 1) * 68 + aRow] = va.y;
                sA[(aK + 2) * 68 + aRow] = va.z;
                sA[(aK + 3) * 68 + aRow] = va.w;
#pragma unroll
                for (int q = 0; q < 4; ++q) {
                    int kk = bC + q * 8;
                    float2 vb = *reinterpret_cast<const float2*>(&Wc[(jb + bRow) * KW + k0 + kk]);
                    sB[(kk + 0) * 68 + bRow] = vb.x;
                    sB[(kk + 1) * 68 + bRow] = vb.y;
                }
                __syncthreads();
#pragma unroll
                for (int k = 0; k < 32; ++k) {
                    float2 a = *reinterpret_cast<const float2*>(&sA[k * 68 + (ty << 1)]);
                    float4 b = *reinterpret_cast<const float4*>(&sB[k * 68 + (tx << 2)]);
                    float2 b01 = make_float2(b.x, b.y);
                    float2 b23 = make_float2(b.z, b.w);
                    float2 pa0 = make_float2(a.x, a.x);
                    float2 pa1 = make_float2(a.y, a.y);
                    acc[0][0] = ffma2(pa0, b01, acc[0][0]);
                    acc[0][1] = ffma2(pa0, b23, acc[0][1]);
                    acc[1][0] = ffma2(pa1, b01, acc[1][0]);
                    acc[1][1] = ffma2(pa1, b23, acc[1][1]);
                }
                __syncthreads();
            }
#pragma unroll
            for (int i = 0; i < 2; ++i) {
                const int b = bm + (ty << 1) + i;
                const int tok = x[b * TT + t];
                const int jcol = jb + (tx << 2);
                const float* pre = &g_pre[2][tok][jcol];
                float vv[4] = {acc[i][0].x, acc[i][0].y, acc[i][1].x, acc[i][1].y};
#pragma unroll
                for (int n = 0; n < 4; ++n) {
                    float v = vv[n] + pre[n];
                    float ht = tanhf(v);
                    int idx = b * HH + jcol + n;
                    float hv = g_h[idx];
                    float zz = g_z[idx];
                    g_h[idx] = hv + zz * (ht - hv);   // (1-z)h + z*ht
                }
            }
        }
        grid_sync(nb);
    }

    // ============ output projection: out[b][c] = h[b] . Wph[c] + bp[c] ===
    const int lane = tid & 31;
    const int warpId = (blockIdx.x << 3) + (tid >> 5);
    const int nWarps = nb << 3;
    for (int oc = warpId; oc < BB * CC; oc += nWarps) {
        const int b = oc / CC;
        const int c = oc - b * CC;
        const float* hrow = &g_h[b * HH];
        const float* wrow = &Wph[c * HH];
        float s = 0.f;
        for (int j = lane; j < HH; j += 32)
            s += hrow[j] * wrow[j];
#pragma unroll
        for (int off = 16; off; off >>= 1)
            s += __shfl_xor_sync(0xffffffffu, s, off);
        if (lane == 0) out[oc] = s + bp[c];
    }
}

// ---------------- launch ---------------------------------------------------
extern "C" void kernel_launch(void* const* d_in, const int* in_sizes, int n_in,
                              void* d_out, int out_size) {
    const int*   x     = (const int*)d_in[0];
    const float* embed = (const float*)d_in[1];
    const float* Wz    = (const float*)d_in[2];
    const float* Wr    = (const float*)d_in[3];
    const float* Wc    = (const float*)d_in[4];
    const float* Wph   = (const float*)d_in[5];
    const float* bp    = (const float*)d_in[6];
    float* out = (float*)d_out;

    int nsm = 0;
    cudaDeviceGetAttribute(&nsm, cudaDevAttrMultiProcessorCount, 0);
    if (nsm <= 0) nsm = 148;

    precompute_kernel<<<(3 * VV * HH + 255) / 256, 256>>>(embed, Wz, Wr, Wc);
    gru_persistent<<<nsm, 256>>>(x, Wz, Wr, Wc, Wph, bp, out, nsm);
}

// round 3
// speedup vs baseline: 1.0008x; 1.0008x over previous
#include <cuda_runtime.h>
#include <math.h>

// Problem constants
#define BB 256      // batch
#define TT 512      // time steps
#define VV 10       // vocab
#define EE 10       // embed dim
#define HH 1024     // hidden
#define CC 10       // out classes
#define KW 1034     // weight row stride (E + H)

// ---------------- device scratch (no allocations allowed) ----------------
__device__ float g_h[BB * HH];            // hidden state
__device__ float g_z[BB * HH];            // z gate scratch
__device__ float g_hr[BB * HH];           // h * r scratch
__device__ float g_pre[3][VV][HH];        // precomputed x-path per token: [z,r,cand]
__device__ unsigned g_count;              // barrier arrival counter (zero-init)
__device__ volatile unsigned g_phase;     // barrier generation

// ---------------- packed fp32x2 FMA (Blackwell full-rate fp32) -----------
__device__ __forceinline__ float2 ffma2(float2 a, float2 b, float2 c) {
    float2 d;
    asm("fma.rn.f32x2 %0, %1, %2, %3;"
        : "=l"(reinterpret_cast<unsigned long long&>(d))
        : "l"(reinterpret_cast<unsigned long long&>(a)),
          "l"(reinterpret_cast<unsigned long long&>(b)),
          "l"(reinterpret_cast<unsigned long long&>(c)));
    return d;
}

// ---------------- grid-wide barrier (all CTAs resident) ------------------
__device__ __forceinline__ void grid_sync(unsigned nb) {
    __syncthreads();
    if (threadIdx.x == 0) {
        __threadfence();                       // push writes to L2 + IVALL
        unsigned ph = g_phase;
        if (atomicAdd(&g_count, 1u) == nb - 1u) {
            g_count = 0u;
            __threadfence();
            g_phase = ph + 1u;                 // release
        } else {
            while (g_phase == ph) { __nanosleep(64); }
        }
        __threadfence();                       // invalidate stale L1 lines
    }
    __syncthreads();
}

// ---------------- precompute x-path tables -------------------------------
// pre[g][v][j] = sum_e embed[v][e] * Wg[j][H + e]
__global__ void precompute_kernel(const float* __restrict__ embed,
                                  const float* __restrict__ Wz,
                                  const float* __restrict__ Wr,
                                  const float* __restrict__ Wc) {
    int idx = blockIdx.x * blockDim.x + threadIdx.x;
    if (idx >= 3 * VV * HH) return;
    int g = idx / (VV * HH);
    int rem = idx - g * (VV * HH);
    int v = rem / HH;
    int j = rem - v * HH;
    const float* Wg = (g == 0) ? Wz : (g == 1) ? Wr : Wc;
    float s = 0.f;
#pragma unroll
    for (int e = 0; e < EE; ++e)
        s += embed[v * EE + e] * Wg[j * KW + HH + e];
    g_pre[g][v][j] = s;
}

// ---------------- persistent GRU kernel ----------------------------------
__global__ void __launch_bounds__(256)
gru_persistent(const int* __restrict__ x,
               const float* __restrict__ Wz,
               const float* __restrict__ Wr,
               const float* __restrict__ Wc,
               const float* __restrict__ Wph,
               const float* __restrict__ bp,
               float* __restrict__ out,
               int nb) {
    __shared__ float sA[32 * 68];   // [k][m], padded to keep 16B alignment
    __shared__ float sB[32 * 68];   // [k][n]

    const int tid = threadIdx.x;
    const int tx = tid & 15;        // n-dim thread coord (x4)
    const int ty = tid >> 4;        // m-dim thread coord

    // zero hidden state (must happen every launch: globals persist)
    for (int i = blockIdx.x * 256 + tid; i < BB * HH; i += nb * 256)
        g_h[i] = 0.f;
    grid_sync(nb);

    for (int t = 0; t < TT; ++t) {
        // ============ phase 1: z and r gates (M=256, N=2048, K=1024) =====
        // 128 tiles of 64x64; tiles 0..63 -> z (Wz), 64..127 -> r (Wr)
        for (int tile = blockIdx.x; tile < 128; tile += nb) {
            const int mt = tile & 3;        // 4 M tiles
            const int nt = tile >> 2;       // 32 N tiles
            const int gate = nt >> 4;       // 0 = z, 1 = r
            const int jb = (nt & 15) << 6;  // col base within gate
            const int bm = mt << 6;         // row base
            const float* __restrict__ Wg = gate ? Wr : Wz;

            float2 acc[4][2];
#pragma unroll
            for (int i = 0; i < 4; ++i) {
                acc[i][0] = make_float2(0.f, 0.f);
                acc[i][1] = make_float2(0.f, 0.f);
            }

            const int aRow = tid >> 3;          // 0..31
            const int aK = (tid & 7) << 2;      // 0,4,..,28
            const int bRow = tid >> 2;          // 0..63
            const int bC = (tid & 3) << 1;      // 0,2,4,6

            for (int k0 = 0; k0 < HH; k0 += 32) {
                // A tile: h[bm..bm+63][k0..k0+31]  (16B-aligned rows)
                float4 va0 = *reinterpret_cast<const float4*>(&g_h[(bm + aRow) * HH + k0 + aK]);
                float4 va1 = *reinterpret_cast<const float4*>(&g_h[(bm + aRow + 32) * HH + k0 + aK]);
                sA[(aK + 0) * 68 + aRow] = va0.x;
                sA[(aK + 1) * 68 + aRow] = va0.y;
                sA[(aK + 2) * 68 + aRow] = va0.z;
                sA[(aK + 3) * 68 + aRow] = va0.w;
                sA[(aK + 0) * 68 + aRow + 32] = va1.x;
                sA[(aK + 1) * 68 + aRow + 32] = va1.y;
                sA[(aK + 2) * 68 + aRow + 32] = va1.z;
                sA[(aK + 3) * 68 + aRow + 32] = va1.w;
                // B tile: Wg[jb..jb+63][k0..k0+31]  (rows only 8B aligned -> float2)
#pragma unroll
                for (int q = 0; q < 4; ++q) {
                    int kk = bC + q * 8;
                    float2 vb = *reinterpret_cast<const float2*>(&Wg[(jb + bRow) * KW + k0 + kk]);
                    sB[(kk + 0) * 68 + bRow] = vb.x;
                    sB[(kk + 1) * 68 + bRow] = vb.y;
                }
                __syncthreads();
#pragma unroll
                for (int k = 0; k < 32; ++k) {
                    float4 a = *reinterpret_cast<const float4*>(&sA[k * 68 + (ty << 2)]);
                    float4 b = *reinterpret_cast<const float4*>(&sB[k * 68 + (tx << 2)]);
                    float2 b01 = make_float2(b.x, b.y);
                    float2 b23 = make_float2(b.z, b.w);
                    float av[4] = {a.x, a.y, a.z, a.w};
#pragma unroll
                    for (int i = 0; i < 4; ++i) {
                        float2 pa = make_float2(av[i], av[i]);
                        acc[i][0] = ffma2(pa, b01, acc[i][0]);
                        acc[i][1] = ffma2(pa, b23, acc[i][1]);
                    }
                }
                __syncthreads();
            }
            // epilogue: sigmoid + store z / hr
#pragma unroll
            for (int i = 0; i < 4; ++i) {
                const int b = bm + (ty << 2) + i;
                const int tok = x[b * TT + t];
                const int jcol = jb + (tx << 2);
                const float* pre = &g_pre[gate][tok][jcol];
                float vv[4] = {acc[i][0].x, acc[i][0].y, acc[i][1].x, acc[i][1].y};
#pragma unroll
                for (int n = 0; n < 4; ++n) {
                    float v = vv[n] + pre[n];
                    float s = 1.f / (1.f + expf(-v));
                    int idx = b * HH + jcol + n;
                    if (gate == 0) g_z[idx] = s;
                    else           g_hr[idx] = s * g_h[idx];
                }
            }
        }
        grid_sync(nb);

        // ============ phase 2: candidate + state update (M=256, N=1024) ==
        // 128 tiles of 32x64
        for (int tile = blockIdx.x; tile < 128; tile += nb) {
            const int mt = tile & 7;        // 8 M tiles of 32
            const int nt = tile >> 3;       // 16 N tiles of 64
            const int bm = mt << 5;
            const int jb = nt << 6;

            float2 acc[2][2];
#pragma unroll
            for (int i = 0; i < 2; ++i) {
                acc[i][0] = make_float2(0.f, 0.f);
                acc[i][1] = make_float2(0.f, 0.f);
            }

            const int aRow = tid >> 3;      // 0..31
            const int aK = (tid & 7) << 2;
            const int bRow = tid >> 2;      // 0..63
            const int bC = (tid & 3) << 1;

            for (int k0 = 0; k0 < HH; k0 += 32) {
                float4 va = *reinterpret_cast<const float4*>(&g_hr[(bm + aRow) * HH + k0 + aK]);
                sA[(aK + 0) * 68 + aRow] = va.x;
                sA[(aK + 1) * 68 + aRow] = va.y;
                sA[(aK + 2) * 68 + aRow] = va.z;
                sA[(aK + 3) * 68 + aRow] = va.w;
#pragma unroll
                for (int q = 0; q < 4; ++q) {
                    int kk = bC + q * 8;
                    float2 vb = *reinterpret_cast<const float2*>(&Wc[(jb + bRow) * KW + k0 + kk]);
                    sB[(kk + 0) * 68 + bRow] = vb.x;
                    sB[(kk + 1) * 68 + bRow] = vb.y;
                }
                __syncthreads();
#pragma unroll
                for (int k = 0; k < 32; ++k) {
                    float2 a = *reinterpret_cast<const float2*>(&sA[k * 68 + (ty << 1)]);
                    float4 b = *reinterpret_cast<const float4*>(&sB[k * 68 + (tx << 2)]);
                    float2 b01 = make_float2(b.x, b.y);
                    float2 b23 = make_float2(b.z, b.w);
                    float2 pa0 = make_float2(a.x, a.x);
                    float2 pa1 = make_float2(a.y, a.y);
                    acc[0][0] = ffma2(pa0, b01, acc[0][0]);
                    acc[0][1] = ffma2(pa0, b23, acc[0][1]);
                    acc[1][0] = ffma2(pa1, b01, acc[1][0]);
                    acc[1][1] = ffma2(pa1, b23, acc[1][1]);
                }
                __syncthreads();
            }
#pragma unroll
            for (int i = 0; i < 2; ++i) {
                const int b = bm + (ty << 1) + i;
                const int tok = x[b * TT + t];
                const int jcol = jb + (tx << 2);
                const float* pre = &g_pre[2][tok][jcol];
                float vv[4] = {acc[i][0].x, acc[i][0].y, acc[i][1].x, acc[i][1].y};
#pragma unroll
                for (int n = 0; n < 4; ++n) {
                    float v = vv[n] + pre[n];
                    float ht = tanhf(v);
                    int idx = b * HH + jcol + n;
                    float hv = g_h[idx];
                    float zz = g_z[idx];
                    g_h[idx] = hv + zz * (ht - hv);   // (1-z)h + z*ht
                }
            }
        }
        grid_sync(nb);
    }

    // ============ output projection: out[b][c] = h[b] . Wph[c] + bp[c] ===
    const int lane = tid & 31;
    const int warpId = (blockIdx.x << 3) + (tid >> 5);
    const int nWarps = nb << 3;
    for (int oc = warpId; oc < BB * CC; oc += nWarps) {
        const int b = oc / CC;
        const int c = oc - b * CC;
        const float* hrow = &g_h[b * HH];
        const float* wrow = &Wph[c * HH];
        float s = 0.f;
        for (int j = lane; j < HH; j += 32)
            s += hrow[j] * wrow[j];
#pragma unroll
        for (int off = 16; off; off >>= 1)
            s += __shfl_xor_sync(0xffffffffu, s, off);
        if (lane == 0) out[oc] = s + bp[c];
    }
}

// ---------------- launch ---------------------------------------------------
extern "C" void kernel_launch(void* const* d_in, const int* in_sizes, int n_in,
                              void* d_out, int out_size) {
    const int*   x     = (const int*)d_in[0];
    const float* embed = (const float*)d_in[1];
    const float* Wz    = (const float*)d_in[2];
    const float* Wr    = (const float*)d_in[3];
    const float* Wc    = (const float*)d_in[4];
    const float* Wph   = (const float*)d_in[5];
    const float* bp    = (const float*)d_in[6];
    float* out = (float*)d_out;

    int nsm = 0;
    cudaDeviceGetAttribute(&nsm, cudaDevAttrMultiProcessorCount, 0);
    if (nsm <= 0) nsm = 148;

    precompute_kernel<<<(3 * VV * HH + 255) / 256, 256>>>(embed, Wz, Wr, Wc);
    gru_persistent<<<nsm, 256>>>(x, Wz, Wr, Wc, Wph, bp, out, nsm);
}

// round 5
// speedup vs baseline: 1.9524x; 1.9508x over previous
#include <cuda_runtime.h>
#include <cuda_bf16.h>
#include <mma.h>
#include <cstdint>
#include <math.h>

using namespace nvcuda;

#define BB 256
#define TT 512
#define VV 10
#define EE 10
#define HH 1024
#define CC 10
#define KW 1034
#define NCTA 128

// ---------------- device scratch ----------------
__device__ float g_h[BB * HH];
__device__ float g_z[BB * HH];
__device__ __nv_bfloat16 g_ha[2][BB * HH];    // h hi/lo   (phase1 A)
__device__ __nv_bfloat16 g_hra[2][BB * HH];   // h*r hi/lo (phase2 A)
__device__ __nv_bfloat16 g_w[3][2][HH * HH];  // weight splits, K-major [j*HH+k]
__device__ float g_pre[3][VV][HH];            // x-path tables
__device__ unsigned g_count;
__device__ volatile unsigned g_phase;

// smem layout: [0..1023] pad; buffer b at 1024 + b*36864:
//   Ahi 64x72 bf16 (9216B) | Alo | Bhi | Blo   (ldm = 72 elems = 144B pitch)
#define BUFSZ   36864
#define MATSZ   9216
#define LDMAB   72
#define LDMC    68
#define SMEM_TOTAL (1024 + 2 * BUFSZ)

typedef wmma::fragment<wmma::accumulator, 16, 16, 16, float> FragC;
typedef wmma::fragment<wmma::matrix_a, 16, 16, 16, __nv_bfloat16, wmma::row_major> FragA;
typedef wmma::fragment<wmma::matrix_b, 16, 16, 16, __nv_bfloat16, wmma::col_major> FragB;

// ---------------- math ----------------
static __device__ __forceinline__ float sigf(float v) {
    return __fdividef(1.f, 1.f + __expf(-v));
}
static __device__ __forceinline__ float fast_tanh(float v) {
    v = fminf(fmaxf(v, -15.f), 15.f);
    float e = __expf(-2.f * v);
    return __fdividef(1.f - e, 1.f + e);
}
static __device__ __forceinline__ uint32_t pack_bf2(float a, float b) {
    __nv_bfloat16 x = __float2bfloat16(a), y = __float2bfloat16(b);
    return ((uint32_t)__bfloat16_as_ushort(y) << 16) | (uint32_t)__bfloat16_as_ushort(x);
}

// ---------------- grid barrier (all 128 CTAs resident) ----------------
static __device__ __forceinline__ void grid_sync() {
    __syncthreads();
    if (threadIdx.x == 0) {
        __threadfence();
        unsigned ph = g_phase;
        if (atomicAdd(&g_count, 1u) == gridDim.x - 1u) {
            g_count = 0u;
            __threadfence();
            g_phase = ph + 1u;
        } else {
            while (g_phase == ph) { __nanosleep(32); }
        }
        __threadfence();
    }
    __syncthreads();
}

// ---------------- precompute: weight hi/lo split + x-path tables ----------
__global__ void precompute_kernel(const float* __restrict__ embed,
                                  const float* __restrict__ Wz,
                                  const float* __restrict__ Wr,
                                  const float* __restrict__ Wc) {
    long idx = (long)blockIdx.x * 256 + threadIdx.x;
    const long NSPLIT = 3L * HH * HH;
    if (idx < NSPLIT) {
        int g = (int)(idx / (HH * HH));
        int rem = (int)(idx % (HH * HH));
        int j = rem / HH, k = rem % HH;
        const float* Wg = (g == 0) ? Wz : (g == 1) ? Wr : Wc;
        float w = Wg[(long)j * KW + k];
        __nv_bfloat16 hi = __float2bfloat16(w);
        g_w[g][0][rem] = hi;
        g_w[g][1][rem] = __float2bfloat16(w - __bfloat162float(hi));
    } else {
        long r = idx - NSPLIT;
        if (r < 3L * VV * HH) {
            int g = (int)(r / (VV * HH));
            int rem = (int)(r % (VV * HH));
            int v = rem / HH, j = rem % HH;
            const float* Wg = (g == 0) ? Wz : (g == 1) ? Wr : Wc;
            float s = 0.f;
#pragma unroll
            for (int e = 0; e < EE; ++e)
                s += embed[v * EE + e] * Wg[(long)j * KW + HH + e];
            g_pre[g][v][j] = s;
        }
    }
}

// ---------------- gmem -> regs -> smem staging (one K=64 chunk) -----------
// 4 matrices x 64 rows x 64 cols bf16; per thread 8 uint4.
// i -> matrix m = i>>1 (compile-time under unroll), rem = tid + (i&1)*256.
static __device__ __forceinline__ void load_regs(
    uint4* pf,
    const __nv_bfloat16* __restrict__ ahi, const __nv_bfloat16* __restrict__ alo,
    const __nv_bfloat16* __restrict__ bhi, const __nv_bfloat16* __restrict__ blo,
    int k0, int tid) {
#pragma unroll
    for (int i = 0; i < 8; ++i) {
        const __nv_bfloat16* base = (i < 2) ? ahi : (i < 4) ? alo : (i < 6) ? bhi : blo;
        int rem = tid + ((i & 1) << 8);
        int row = rem >> 3, c = rem & 7;
        pf[i] = *reinterpret_cast<const uint4*>(base + (long)row * HH + k0 + (c << 3));
    }
}
static __device__ __forceinline__ void store_regs(char* buf, const uint4* pf, int tid) {
#pragma unroll
    for (int i = 0; i < 8; ++i) {
        int rem = tid + ((i & 1) << 8);
        int row = rem >> 3, c = rem & 7;
        *reinterpret_cast<uint4*>(buf + (i >> 1) * MATSZ + row * 144 + (c << 4)) = pf[i];
    }
}

// ---------------- compute one K=64 chunk (bf16x3) ----------------
static __device__ __forceinline__ void compute_chunk(
    const char* buf, int wm, int wn, FragC& c0, FragC& c1) {
    const __nv_bfloat16* Ah = reinterpret_cast<const __nv_bfloat16*>(buf);
    const __nv_bfloat16* Al = reinterpret_cast<const __nv_bfloat16*>(buf + MATSZ);
    const __nv_bfloat16* Bh = reinterpret_cast<const __nv_bfloat16*>(buf + 2 * MATSZ);
    const __nv_bfloat16* Bl = reinterpret_cast<const __nv_bfloat16*>(buf + 3 * MATSZ);
#pragma unroll
    for (int ks = 0; ks < 4; ++ks) {
        FragA ah0, ah1, al0, al1;
        FragB bh, bl;
        wmma::load_matrix_sync(ah0, Ah + (wm * 32) * LDMAB + ks * 16, LDMAB);
        wmma::load_matrix_sync(ah1, Ah + (wm * 32 + 16) * LDMAB + ks * 16, LDMAB);
        wmma::load_matrix_sync(al0, Al + (wm * 32) * LDMAB + ks * 16, LDMAB);
        wmma::load_matrix_sync(al1, Al + (wm * 32 + 16) * LDMAB + ks * 16, LDMAB);
        wmma::load_matrix_sync(bh, Bh + (wn * 16) * LDMAB + ks * 16, LDMAB);
        wmma::load_matrix_sync(bl, Bl + (wn * 16) * LDMAB + ks * 16, LDMAB);
        wmma::mma_sync(c0, ah0, bh, c0);
        wmma::mma_sync(c1, ah1, bh, c1);
        wmma::mma_sync(c0, ah0, bl, c0);
        wmma::mma_sync(c1, ah1, bl, c1);
        wmma::mma_sync(c0, al0, bh, c0);
        wmma::mma_sync(c1, al1, bh, c1);
    }
}

// ---------------- one 64x64x1024 GEMM, double-buffered ----------------
static __device__ void run_gemm(
    char* sm,
    const __nv_bfloat16* __restrict__ ahi, const __nv_bfloat16* __restrict__ alo,
    const __nv_bfloat16* __restrict__ bhi, const __nv_bfloat16* __restrict__ blo,
    int tid, int wid, FragC& c0, FragC& c1) {
    wmma::fill_fragment(c0, 0.f);
    wmma::fill_fragment(c1, 0.f);
    const int wm = wid & 1, wn = wid >> 1;
    uint4 pf[8];
    load_regs(pf, ahi, alo, bhi, blo, 0, tid);
    store_regs(sm + 1024, pf, tid);
    __syncthreads();
#pragma unroll 1
    for (int c = 0; c < 16; ++c) {
        if (c < 15) load_regs(pf, ahi, alo, bhi, blo, (c + 1) * 64, tid);
        compute_chunk(sm + 1024 + (c & 1) * BUFSZ, wm, wn, c0, c1);
        __syncthreads();
        if (c < 15) {
            store_regs(sm + 1024 + ((c + 1) & 1) * BUFSZ, pf, tid);
            __syncthreads();
        }
    }
}

// ---------------- main persistent kernel ----------------
__global__ void __launch_bounds__(256, 1)
gru_tc(const int* __restrict__ x,
       const float* __restrict__ Wph,
       const float* __restrict__ bp,
       float* __restrict__ out) {
    extern __shared__ __align__(16) char smem[];
    const int tid = threadIdx.x;
    const int wid = tid >> 5;
    const int lane = tid & 31;
    const int cta = blockIdx.x;
    const int wm = wid & 1, wn = wid >> 1;

    // reset recurrent state (globals persist across graph replays)
    for (int i = cta * 256 + tid; i < BB * HH; i += NCTA * 256) {
        g_h[i] = 0.f;
        g_ha[0][i] = __float2bfloat16(0.f);
        g_ha[1][i] = __float2bfloat16(0.f);
    }
    grid_sync();

    // phase1: 128 tiles = 4 M-strips(64) x (16 z + 16 r) N-tiles(64)
    const int p1_bm = (cta & 3) << 6;
    const int p1_nt = cta >> 2;
    const int p1_gate = p1_nt >> 4;
    const int p1_jb = (p1_nt & 15) << 6;
    // phase2: 64 tiles = 4 M-strips x 16 N-tiles (ctas 0..63)
    const int p2_bm = (cta & 3) << 6;
    const int p2_jb = (cta >> 2) << 6;

    float* sC = reinterpret_cast<float*>(smem + 1024);
    const int er = tid >> 2;                 // epilogue row 0..63
    const int ecb = (tid & 3) << 4;          // epilogue col base (16 cols)

    FragC c0, c1;

    for (int t = 0; t < TT; ++t) {
        // ============ phase 1: z / r gates ============
        run_gemm(smem,
                 &g_ha[0][p1_bm * HH], &g_ha[1][p1_bm * HH],
                 &g_w[p1_gate][0][p1_jb * HH], &g_w[p1_gate][1][p1_jb * HH],
                 tid, wid, c0, c1);
        wmma::store_matrix_sync(sC + (wm * 32) * LDMC + wn * 16, c0, LDMC, wmma::mem_row_major);
        wmma::store_matrix_sync(sC + (wm * 32 + 16) * LDMC + wn * 16, c1, LDMC, wmma::mem_row_major);
        __syncthreads();
        {
            const int b = p1_bm + er;
            const int tok = x[b * TT + t];
            const float* __restrict__ pre = &g_pre[p1_gate][tok][p1_jb + ecb];
            const float* __restrict__ cr = sC + er * LDMC + ecb;
            if (p1_gate == 0) {
                float* __restrict__ dst = &g_z[b * HH + p1_jb + ecb];
#pragma unroll
                for (int q = 0; q < 4; ++q) {
                    float4 v = *reinterpret_cast<const float4*>(cr + q * 4);
                    float4 p = *reinterpret_cast<const float4*>(pre + q * 4);
                    float4 o;
                    o.x = sigf(v.x + p.x);
                    o.y = sigf(v.y + p.y);
                    o.z = sigf(v.z + p.z);
                    o.w = sigf(v.w + p.w);
                    *reinterpret_cast<float4*>(dst + q * 4) = o;
                }
            } else {
                const float* __restrict__ hrow = &g_h[b * HH + p1_jb + ecb];
                float hr[16];
#pragma unroll
                for (int q = 0; q < 4; ++q) {
                    float4 v = *reinterpret_cast<const float4*>(cr + q * 4);
                    float4 p = *reinterpret_cast<const float4*>(pre + q * 4);
                    float4 h4 = *reinterpret_cast<const float4*>(hrow + q * 4);
                    hr[q * 4 + 0] = sigf(v.x + p.x) * h4.x;
                    hr[q * 4 + 1] = sigf(v.y + p.y) * h4.y;
                    hr[q * 4 + 2] = sigf(v.z + p.z) * h4.z;
                    hr[q * 4 + 3] = sigf(v.w + p.w) * h4.w;
                }
                uint32_t phi[8], plo[8];
#pragma unroll
                for (int q = 0; q < 8; ++q) {
                    float a = hr[2 * q], bx = hr[2 * q + 1];
                    float ea = a - __bfloat162float(__float2bfloat16(a));
                    float eb = bx - __bfloat162float(__float2bfloat16(bx));
                    phi[q] = pack_bf2(a, bx);
                    plo[q] = pack_bf2(ea, eb);
                }
                uint4* dhi = reinterpret_cast<uint4*>(&g_hra[0][b * HH + p1_jb + ecb]);
                uint4* dlo = reinterpret_cast<uint4*>(&g_hra[1][b * HH + p1_jb + ecb]);
                dhi[0] = make_uint4(phi[0], phi[1], phi[2], phi[3]);
                dhi[1] = make_uint4(phi[4], phi[5], phi[6], phi[7]);
                dlo[0] = make_uint4(plo[0], plo[1], plo[2], plo[3]);
                dlo[1] = make_uint4(plo[4], plo[5], plo[6], plo[7]);
            }
        }
        grid_sync();

        // ============ phase 2: candidate + state update ============
        if (cta < 64) {
            run_gemm(smem,
                     &g_hra[0][p2_bm * HH], &g_hra[1][p2_bm * HH],
                     &g_w[2][0][p2_jb * HH], &g_w[2][1][p2_jb * HH],
                     tid, wid, c0, c1);
            wmma::store_matrix_sync(sC + (wm * 32) * LDMC + wn * 16, c0, LDMC, wmma::mem_row_major);
            wmma::store_matrix_sync(sC + (wm * 32 + 16) * LDMC + wn * 16, c1, LDMC, wmma::mem_row_major);
            __syncthreads();
            {
                const int b = p2_bm + er;
                const int tok = x[b * TT + t];
                const float* __restrict__ pre = &g_pre[2][tok][p2_jb + ecb];
                const float* __restrict__ cr = sC + er * LDMC + ecb;
                float* __restrict__ hrow = &g_h[b * HH + p2_jb + ecb];
                const float* __restrict__ zrow = &g_z[b * HH + p2_jb + ecb];
                float hn[16];
#pragma unroll
                for (int q = 0; q < 4; ++q) {
                    float4 v = *reinterpret_cast<const float4*>(cr + q * 4);
                    float4 p = *reinterpret_cast<const float4*>(pre + q * 4);
                    float4 h4 = *reinterpret_cast<const float4*>(hrow + q * 4);
                    float4 z4 = *reinterpret_cast<const float4*>(zrow + q * 4);
                    hn[q * 4 + 0] = h4.x + z4.x * (fast_tanh(v.x + p.x) - h4.x);
                    hn[q * 4 + 1] = h4.y + z4.y * (fast_tanh(v.y + p.y) - h4.y);
                    hn[q * 4 + 2] = h4.z + z4.z * (fast_tanh(v.z + p.z) - h4.z);
                    hn[q * 4 + 3] = h4.w + z4.w * (fast_tanh(v.w + p.w) - h4.w);
                }
#pragma unroll
                for (int q = 0; q < 4; ++q)
                    *reinterpret_cast<float4*>(hrow + q * 4) =
                        make_float4(hn[q * 4], hn[q * 4 + 1], hn[q * 4 + 2], hn[q * 4 + 3]);
                uint32_t phi[8], plo[8];
#pragma unroll
                for (int q = 0; q < 8; ++q) {
                    float a = hn[2 * q], bx = hn[2 * q + 1];
                    float ea = a - __bfloat162float(__float2bfloat16(a));
                    float eb = bx - __bfloat162float(__float2bfloat16(bx));
                    phi[q] = pack_bf2(a, bx);
                    plo[q] = pack_bf2(ea, eb);
                }
                uint4* dhi = reinterpret_cast<uint4*>(&g_ha[0][b * HH + p2_jb + ecb]);
                uint4* dlo = reinterpret_cast<uint4*>(&g_ha[1][b * HH + p2_jb + ecb]);
                dhi[0] = make_uint4(phi[0], phi[1], phi[2], phi[3]);
                dhi[1] = make_uint4(phi[4], phi[5], phi[6], phi[7]);
                dlo[0] = make_uint4(plo[0], plo[1], plo[2], plo[3]);
                dlo[1] = make_uint4(plo[4], plo[5], plo[6], plo[7]);
            }
        }
        grid_sync();
    }

    // ============ output projection ============
    const int warpId = (cta << 3) + wid;
    const int nWarps = NCTA << 3;
    for (int oc = warpId; oc < BB * CC; oc += nWarps) {
        const int b = oc / CC;
        const int c = oc - b * CC;
        const float* hrow = &g_h[b * HH];
        const float* wrow = &Wph[c * HH];
        float s = 0.f;
        for (int j = lane; j < HH; j += 32)
            s += hrow[j] * wrow[j];
#pragma unroll
        for (int off = 16; off; off >>= 1)
            s += __shfl_xor_sync(0xffffffffu, s, off);
        if (lane == 0) out[oc] = s + bp[c];
    }
}

// ---------------- launch ----------------
extern "C" void kernel_launch(void* const* d_in, const int* in_sizes, int n_in,
                              void* d_out, int out_size) {
    const int*   x     = (const int*)d_in[0];
    const float* embed = (const float*)d_in[1];
    const float* Wz    = (const float*)d_in[2];
    const float* Wr    = (const float*)d_in[3];
    const float* Wc    = (const float*)d_in[4];
    const float* Wph   = (const float*)d_in[5];
    const float* bp    = (const float*)d_in[6];
    float* out = (float*)d_out;

    cudaFuncSetAttribute(gru_tc, cudaFuncAttributeMaxDynamicSharedMemorySize, SMEM_TOTAL);

    const long total = 3L * HH * HH + 3L * VV * HH;
    precompute_kernel<<<(unsigned)((total + 255) / 256), 256>>>(embed, Wz, Wr, Wc);
    gru_tc<<<NCTA, 256, SMEM_TOTAL>>>(x, Wph, bp, out);
}

// round 6
// speedup vs baseline: 2.1349x; 1.0934x over previous
#include <cuda_runtime.h>
#include <cuda_bf16.h>
#include <mma.h>
#include <cstdint>
#include <math.h>

using namespace nvcuda;

#define BB 256
#define TT 512
#define VV 10
#define EE 10
#define HH 1024
#define CC 10
#define KW 1034
#define NCTA 128
#define STAGES 3

// ---------------- device scratch ----------------
__device__ float g_h[BB * HH];
__device__ float g_z[BB * HH];
__device__ __nv_bfloat16 g_ha[2][BB * HH];    // h hi/lo   (phase1 A)
__device__ __nv_bfloat16 g_hra[2][BB * HH];   // h*r hi/lo (phase2 A)
__device__ __nv_bfloat16 g_w[3][2][HH * HH];  // weight splits, K-major [j*HH+k]
__device__ float g_pre[3][VV][HH];            // x-path tables
__device__ unsigned g_count;
__device__ volatile unsigned g_phase;

// smem: [0..1023] pad; stage s at 1024 + s*36864:
//   Ahi 64x72 bf16 (9216B) | Alo | Bhi | Blo   (row pitch 144B)
#define BUFSZ   36864
#define MATSZ   9216
#define LDMAB   72
#define LDMC    68
#define SMEM_TOTAL (1024 + STAGES * BUFSZ)

typedef wmma::fragment<wmma::accumulator, 16, 16, 16, float> FragC;
typedef wmma::fragment<wmma::matrix_a, 16, 16, 16, __nv_bfloat16, wmma::row_major> FragA;
typedef wmma::fragment<wmma::matrix_b, 16, 16, 16, __nv_bfloat16, wmma::col_major> FragB;

// ---------------- math ----------------
static __device__ __forceinline__ float sigf(float v) {
    return __fdividef(1.f, 1.f + __expf(-v));
}
static __device__ __forceinline__ float fast_tanh(float v) {
    v = fminf(fmaxf(v, -15.f), 15.f);
    float e = __expf(-2.f * v);
    return __fdividef(1.f - e, 1.f + e);
}
static __device__ __forceinline__ uint32_t pack_bf2(float a, float b) {
    __nv_bfloat16 x = __float2bfloat16(a), y = __float2bfloat16(b);
    return ((uint32_t)__bfloat16_as_ushort(y) << 16) | (uint32_t)__bfloat16_as_ushort(x);
}
static __device__ __forceinline__ uint32_t smem_u32(const void* p) {
    uint32_t a;
    asm("{ .reg .u64 t; cvta.to.shared.u64 t, %1; cvt.u32.u64 %0, t; }" : "=r"(a) : "l"(p));
    return a;
}

// ---------------- grid barrier ----------------
static __device__ __forceinline__ void grid_sync() {
    __syncthreads();
    if (threadIdx.x == 0) {
        __threadfence();
        unsigned ph = g_phase;
        if (atomicAdd(&g_count, 1u) == gridDim.x - 1u) {
            g_count = 0u;
            __threadfence();
            g_phase = ph + 1u;
        } else {
            while (g_phase == ph) { __nanosleep(32); }
        }
        __threadfence();
    }
    __syncthreads();
}

// ---------------- precompute: weight hi/lo split + x-path tables ----------
__global__ void precompute_kernel(const float* __restrict__ embed,
                                  const float* __restrict__ Wz,
                                  const float* __restrict__ Wr,
                                  const float* __restrict__ Wc) {
    long idx = (long)blockIdx.x * 256 + threadIdx.x;
    const long NSPLIT = 3L * HH * HH;
    if (idx < NSPLIT) {
        int g = (int)(idx / (HH * HH));
        int rem = (int)(idx % (HH * HH));
        int j = rem / HH, k = rem % HH;
        const float* Wg = (g == 0) ? Wz : (g == 1) ? Wr : Wc;
        float w = Wg[(long)j * KW + k];
        __nv_bfloat16 hi = __float2bfloat16(w);
        g_w[g][0][rem] = hi;
        g_w[g][1][rem] = __float2bfloat16(w - __bfloat162float(hi));
    } else {
        long r = idx - NSPLIT;
        if (r < 3L * VV * HH) {
            int g = (int)(r / (VV * HH));
            int rem = (int)(r % (VV * HH));
            int v = rem / HH, j = rem % HH;
            const float* Wg = (g == 0) ? Wz : (g == 1) ? Wr : Wc;
            float s = 0.f;
#pragma unroll
            for (int e = 0; e < EE; ++e)
                s += embed[v * EE + e] * Wg[(long)j * KW + HH + e];
            g_pre[g][v][j] = s;
        }
    }
}

// ---------------- cp.async stage issue: one K=64 chunk -> one stage -------
// 4 matrices x 64 rows x 64 cols bf16; per thread 8 x 16B cp.async.
static __device__ __forceinline__ void issue_stage(
    uint32_t sbuf,
    const __nv_bfloat16* __restrict__ ahi, const __nv_bfloat16* __restrict__ alo,
    const __nv_bfloat16* __restrict__ bhi, const __nv_bfloat16* __restrict__ blo,
    int k0, int tid) {
#pragma unroll
    for (int i = 0; i < 8; ++i) {
        const __nv_bfloat16* base = (i < 2) ? ahi : (i < 4) ? alo : (i < 6) ? bhi : blo;
        int rem = tid + ((i & 1) << 8);
        int row = rem >> 3, c = rem & 7;
        const void* src = base + (long)row * HH + k0 + (c << 3);
        uint32_t dst = sbuf + (i >> 1) * MATSZ + row * 144 + (c << 4);
        asm volatile("cp.async.cg.shared.global [%0], [%1], 16;" :: "r"(dst), "l"(src));
    }
    asm volatile("cp.async.commit_group;" ::: "memory");
}

// ---------------- compute one K=64 chunk (bf16x3, split accumulators) -----
static __device__ __forceinline__ void compute_chunk(
    const char* buf, int wm, int wn,
    FragC& c0h, FragC& c0m, FragC& c1h, FragC& c1m) {
    const __nv_bfloat16* Ah = reinterpret_cast<const __nv_bfloat16*>(buf);
    const __nv_bfloat16* Al = reinterpret_cast<const __nv_bfloat16*>(buf + MATSZ);
    const __nv_bfloat16* Bh = reinterpret_cast<const __nv_bfloat16*>(buf + 2 * MATSZ);
    const __nv_bfloat16* Bl = reinterpret_cast<const __nv_bfloat16*>(buf + 3 * MATSZ);
#pragma unroll
    for (int ks = 0; ks < 4; ++ks) {
        FragA ah0, ah1, al0, al1;
        FragB bh, bl;
        wmma::load_matrix_sync(ah0, Ah + (wm * 32) * LDMAB + ks * 16, LDMAB);
        wmma::load_matrix_sync(ah1, Ah + (wm * 32 + 16) * LDMAB + ks * 16, LDMAB);
        wmma::load_matrix_sync(bh, Bh + (wn * 16) * LDMAB + ks * 16, LDMAB);
        wmma::load_matrix_sync(bl, Bl + (wn * 16) * LDMAB + ks * 16, LDMAB);
        wmma::load_matrix_sync(al0, Al + (wm * 32) * LDMAB + ks * 16, LDMAB);
        wmma::load_matrix_sync(al1, Al + (wm * 32 + 16) * LDMAB + ks * 16, LDMAB);
        // 4 independent accumulator chains
        wmma::mma_sync(c0h, ah0, bh, c0h);
        wmma::mma_sync(c1h, ah1, bh, c1h);
        wmma::mma_sync(c0m, ah0, bl, c0m);
        wmma::mma_sync(c1m, ah1, bl, c1m);
        wmma::mma_sync(c0m, al0, bh, c0m);
        wmma::mma_sync(c1m, al1, bh, c1m);
    }
}

// ---------------- one 64x64x1024 GEMM, 3-stage cp.async pipeline ----------
static __device__ void run_gemm(
    char* sm, uint32_t sbase,
    const __nv_bfloat16* __restrict__ ahi, const __nv_bfloat16* __restrict__ alo,
    const __nv_bfloat16* __restrict__ bhi, const __nv_bfloat16* __restrict__ blo,
    int tid, int wid, FragC& c0, FragC& c1) {
    FragC c0m, c1m;
    wmma::fill_fragment(c0, 0.f);
    wmma::fill_fragment(c1, 0.f);
    wmma::fill_fragment(c0m, 0.f);
    wmma::fill_fragment(c1m, 0.f);
    const int wm = wid & 1, wn = wid >> 1;

    // prologue: prefetch chunks 0..STAGES-2
    issue_stage(sbase + 1024, ahi, alo, bhi, blo, 0, tid);
    issue_stage(sbase + 1024 + BUFSZ, ahi, alo, bhi, blo, 64, tid);

#pragma unroll 1
    for (int c = 0; c < 16; ++c) {
        if (c < 14) asm volatile("cp.async.wait_group 1;" ::: "memory");
        else        asm volatile("cp.async.wait_group 0;" ::: "memory");
        __syncthreads();
        // prefetch chunk c+2 into the stage computed at iter c-1 (safe: sync above)
        if (c < 14)
            issue_stage(sbase + 1024 + ((c + 2) % STAGES) * BUFSZ,
                        ahi, alo, bhi, blo, (c + 2) * 64, tid);
        compute_chunk(sm + 1024 + (c % STAGES) * BUFSZ, wm, wn, c0, c0m, c1, c1m);
    }
    // merge split accumulators
#pragma unroll
    for (int i = 0; i < c0.num_elements; ++i) {
        c0.x[i] += c0m.x[i];
        c1.x[i] += c1m.x[i];
    }
    __syncthreads();   // all warps done reading stages before epilogue reuses smem
}

// ---------------- main persistent kernel ----------------
__global__ void __launch_bounds__(256, 1)
gru_tc(const int* __restrict__ x,
       const float* __restrict__ Wph,
       const float* __restrict__ bp,
       float* __restrict__ out) {
    extern __shared__ __align__(16) char smem[];
    const uint32_t sbase = smem_u32(smem);
    const int tid = threadIdx.x;
    const int wid = tid >> 5;
    const int lane = tid & 31;
    const int cta = blockIdx.x;
    const int wm = wid & 1, wn = wid >> 1;

    // reset recurrent state (globals persist across graph replays)
    for (int i = cta * 256 + tid; i < BB * HH; i += NCTA * 256) {
        g_h[i] = 0.f;
        g_ha[0][i] = __float2bfloat16(0.f);
        g_ha[1][i] = __float2bfloat16(0.f);
    }
    grid_sync();

    // phase1: 128 tiles = 4 M-strips(64) x (16 z + 16 r) N-tiles(64)
    const int p1_bm = (cta & 3) << 6;
    const int p1_nt = cta >> 2;
    const int p1_gate = p1_nt >> 4;
    const int p1_jb = (p1_nt & 15) << 6;
    // phase2: 64 tiles = 4 M-strips x 16 N-tiles (ctas 0..63)
    const int p2_bm = (cta & 3) << 6;
    const int p2_jb = (cta >> 2) << 6;

    float* sC = reinterpret_cast<float*>(smem + 1024);
    const int er = tid >> 2;                 // epilogue row 0..63
    const int ecb = (tid & 3) << 4;          // epilogue col base (16 cols)

    FragC c0, c1;

    for (int t = 0; t < TT; ++t) {
        // ============ phase 1: z / r gates ============
        run_gemm(smem, sbase,
                 &g_ha[0][p1_bm * HH], &g_ha[1][p1_bm * HH],
                 &g_w[p1_gate][0][p1_jb * HH], &g_w[p1_gate][1][p1_jb * HH],
                 tid, wid, c0, c1);
        wmma::store_matrix_sync(sC + (wm * 32) * LDMC + wn * 16, c0, LDMC, wmma::mem_row_major);
        wmma::store_matrix_sync(sC + (wm * 32 + 16) * LDMC + wn * 16, c1, LDMC, wmma::mem_row_major);
        __syncthreads();
        {
            const int b = p1_bm + er;
            const int tok = x[b * TT + t];
            const float* __restrict__ pre = &g_pre[p1_gate][tok][p1_jb + ecb];
            const float* __restrict__ cr = sC + er * LDMC + ecb;
            if (p1_gate == 0) {
                float* __restrict__ dst = &g_z[b * HH + p1_jb + ecb];
#pragma unroll
                for (int q = 0; q < 4; ++q) {
                    float4 v = *reinterpret_cast<const float4*>(cr + q * 4);
                    float4 p = *reinterpret_cast<const float4*>(pre + q * 4);
                    float4 o;
                    o.x = sigf(v.x + p.x);
                    o.y = sigf(v.y + p.y);
                    o.z = sigf(v.z + p.z);
                    o.w = sigf(v.w + p.w);
                    *reinterpret_cast<float4*>(dst + q * 4) = o;
                }
            } else {
                const float* __restrict__ hrow = &g_h[b * HH + p1_jb + ecb];
                float hr[16];
#pragma unroll
                for (int q = 0; q < 4; ++q) {
                    float4 v = *reinterpret_cast<const float4*>(cr + q * 4);
                    float4 p = *reinterpret_cast<const float4*>(pre + q * 4);
                    float4 h4 = *reinterpret_cast<const float4*>(hrow + q * 4);
                    hr[q * 4 + 0] = sigf(v.x + p.x) * h4.x;
                    hr[q * 4 + 1] = sigf(v.y + p.y) * h4.y;
                    hr[q * 4 + 2] = sigf(v.z + p.z) * h4.z;
                    hr[q * 4 + 3] = sigf(v.w + p.w) * h4.w;
                }
                uint32_t phi[8], plo[8];
#pragma unroll
                for (int q = 0; q < 8; ++q) {
                    float a = hr[2 * q], bx = hr[2 * q + 1];
                    float ea = a - __bfloat162float(__float2bfloat16(a));
                    float eb = bx - __bfloat162float(__float2bfloat16(bx));
                    phi[q] = pack_bf2(a, bx);
                    plo[q] = pack_bf2(ea, eb);
                }
                uint4* dhi = reinterpret_cast<uint4*>(&g_hra[0][b * HH + p1_jb + ecb]);
                uint4* dlo = reinterpret_cast<uint4*>(&g_hra[1][b * HH + p1_jb + ecb]);
                dhi[0] = make_uint4(phi[0], phi[1], phi[2], phi[3]);
                dhi[1] = make_uint4(phi[4], phi[5], phi[6], phi[7]);
                dlo[0] = make_uint4(plo[0], plo[1], plo[2], plo[3]);
                dlo[1] = make_uint4(plo[4], plo[5], plo[6], plo[7]);
            }
        }
        grid_sync();

        // ============ phase 2: candidate + state update ============
        if (cta < 64) {
            run_gemm(smem, sbase,
                     &g_hra[0][p2_bm * HH], &g_hra[1][p2_bm * HH],
                     &g_w[2][0][p2_jb * HH], &g_w[2][1][p2_jb * HH],
                     tid, wid, c0, c1);
            wmma::store_matrix_sync(sC + (wm * 32) * LDMC + wn * 16, c0, LDMC, wmma::mem_row_major);
            wmma::store_matrix_sync(sC + (wm * 32 + 16) * LDMC + wn * 16, c1, LDMC, wmma::mem_row_major);
            __syncthreads();
            {
                const int b = p2_bm + er;
                const int tok = x[b * TT + t];
                const float* __restrict__ pre = &g_pre[2][tok][p2_jb + ecb];
                const float* __restrict__ cr = sC + er * LDMC + ecb;
                float* __restrict__ hrow = &g_h[b * HH + p2_jb + ecb];
                const float* __restrict__ zrow = &g_z[b * HH + p2_jb + ecb];
                float hn[16];
#pragma unroll
                for (int q = 0; q < 4; ++q) {
                    float4 v = *reinterpret_cast<const float4*>(cr + q * 4);
                    float4 p = *reinterpret_cast<const float4*>(pre + q * 4);
                    float4 h4 = *reinterpret_cast<const float4*>(hrow + q * 4);
                    float4 z4 = *reinterpret_cast<const float4*>(zrow + q * 4);
                    hn[q * 4 + 0] = h4.x + z4.x * (fast_tanh(v.x + p.x) - h4.x);
                    hn[q * 4 + 1] = h4.y + z4.y * (fast_tanh(v.y + p.y) - h4.y);
                    hn[q * 4 + 2] = h4.z + z4.z * (fast_tanh(v.z + p.z) - h4.z);
                    hn[q * 4 + 3] = h4.w + z4.w * (fast_tanh(v.w + p.w) - h4.w);
                }
#pragma unroll
                for (int q = 0; q < 4; ++q)
                    *reinterpret_cast<float4*>(hrow + q * 4) =
                        make_float4(hn[q * 4], hn[q * 4 + 1], hn[q * 4 + 2], hn[q * 4 + 3]);
                uint32_t phi[8], plo[8];
#pragma unroll
                for (int q = 0; q < 8; ++q) {
                    float a = hn[2 * q], bx = hn[2 * q + 1];
                    float ea = a - __bfloat162float(__float2bfloat16(a));
                    float eb = bx - __bfloat162float(__float2bfloat16(bx));
                    phi[q] = pack_bf2(a, bx);
                    plo[q] = pack_bf2(ea, eb);
                }
                uint4* dhi = reinterpret_cast<uint4*>(&g_ha[0][b * HH + p2_jb + ecb]);
                uint4* dlo = reinterpret_cast<uint4*>(&g_ha[1][b * HH + p2_jb + ecb]);
                dhi[0] = make_uint4(phi[0], phi[1], phi[2], phi[3]);
                dhi[1] = make_uint4(phi[4], phi[5], phi[6], phi[7]);
                dlo[0] = make_uint4(plo[0], plo[1], plo[2], plo[3]);
                dlo[1] = make_uint4(plo[4], plo[5], plo[6], plo[7]);
            }
        }
        grid_sync();
    }

    // ============ output projection ============
    const int warpId = (cta << 3) + wid;
    const int nWarps = NCTA << 3;
    for (int oc = warpId; oc < BB * CC; oc += nWarps) {
        const int b = oc / CC;
        const int c = oc - b * CC;
        const float* hrow = &g_h[b * HH];
        const float* wrow = &Wph[c * HH];
        float s = 0.f;
        for (int j = lane; j < HH; j += 32)
            s += hrow[j] * wrow[j];
#pragma unroll
        for (int off = 16; off; off >>= 1)
            s += __shfl_xor_sync(0xffffffffu, s, off);
        if (lane == 0) out[oc] = s + bp[c];
    }
}

// ---------------- launch ----------------
extern "C" void kernel_launch(void* const* d_in, const int* in_sizes, int n_in,
                              void* d_out, int out_size) {
    const int*   x     = (const int*)d_in[0];
    const float* embed = (const float*)d_in[1];
    const float* Wz    = (const float*)d_in[2];
    const float* Wr    = (const float*)d_in[3];
    const float* Wc    = (const float*)d_in[4];
    const float* Wph   = (const float*)d_in[5];
    const float* bp    = (const float*)d_in[6];
    float* out = (float*)d_out;

    cudaFuncSetAttribute(gru_tc, cudaFuncAttributeMaxDynamicSharedMemorySize, SMEM_TOTAL);

    const long total = 3L * HH * HH + 3L * VV * HH;
    precompute_kernel<<<(unsigned)((total + 255) / 256), 256>>>(embed, Wz, Wr, Wc);
    gru_tc<<<NCTA, 256, SMEM_TOTAL>>>(x, Wph, bp, out);
}

// round 7
// speedup vs baseline: 2.5927x; 1.2145x over previous
#include <cuda_runtime.h>
#include <cuda_bf16.h>
#include <mma.h>
#include <cstdint>
#include <math.h>

using namespace nvcuda;

#define BB 256
#define TT 512
#define VV 10
#define EE 10
#define HH 1024
#define CC 10
#define KW 1034
#define NCTA 128
#define NTHR 512

// ---------------- device scratch ----------------
__device__ float g_h[BB * HH];
__device__ float g_z[BB * HH];
__device__ __nv_bfloat16 g_ha[2][BB * HH];    // h hi/lo   (phase1 A)
__device__ __nv_bfloat16 g_hra[2][BB * HH];   // h*r hi/lo (phase2 A)
__device__ __nv_bfloat16 g_w[3][2][HH * HH];  // weight splits, K-major [j*HH+k]
__device__ float g_pre[3][VV][HH];            // x-path tables
__device__ unsigned g_count;
__device__ volatile unsigned g_phase;

// phase1 stage (stride 36864): Ahi 64x72 | Alo | Bhi | Blo   (pitch 144B)
// phase2 stage (stride 55296): Ahi0 32x72 | Alo0 | Ahi1 | Alo1 | Bhi0 64x72 | Blo0 | Bhi1 | Blo1
#define P1STRIDE 36864
#define P2STRIDE 55296
#define MATSZ    9216
#define LDMAB    72
#define LDMC     68
#define SMEM_TOTAL (1024 + 110592)

typedef wmma::fragment<wmma::accumulator, 16, 16, 16, float> FragC;
typedef wmma::fragment<wmma::matrix_a, 16, 16, 16, __nv_bfloat16, wmma::row_major> FragA;
typedef wmma::fragment<wmma::matrix_b, 16, 16, 16, __nv_bfloat16, wmma::col_major> FragB;

// ---------------- math ----------------
static __device__ __forceinline__ float sigf(float v) {
    return __fdividef(1.f, 1.f + __expf(-v));
}
static __device__ __forceinline__ float fast_tanh(float v) {
    v = fminf(fmaxf(v, -15.f), 15.f);
    float e = __expf(-2.f * v);
    return __fdividef(1.f - e, 1.f + e);
}
static __device__ __forceinline__ uint32_t pack_bf2(float a, float b) {
    __nv_bfloat16 x = __float2bfloat16(a), y = __float2bfloat16(b);
    return ((uint32_t)__bfloat16_as_ushort(y) << 16) | (uint32_t)__bfloat16_as_ushort(x);
}
static __device__ __forceinline__ uint32_t smem_u32(const void* p) {
    uint32_t a;
    asm("{ .reg .u64 t; cvta.to.shared.u64 t, %1; cvt.u32.u64 %0, t; }" : "=r"(a) : "l"(p));
    return a;
}

// ---------------- grid barrier ----------------
static __device__ __forceinline__ void grid_sync() {
    __syncthreads();
    if (threadIdx.x == 0) {
        __threadfence();
        unsigned ph = g_phase;
        if (atomicAdd(&g_count, 1u) == gridDim.x - 1u) {
            g_count = 0u;
            __threadfence();
            g_phase = ph + 1u;
        } else {
            while (g_phase == ph) { __nanosleep(32); }
        }
        __threadfence();
    }
    __syncthreads();
}

// ---------------- precompute ----------------
__global__ void precompute_kernel(const float* __restrict__ embed,
                                  const float* __restrict__ Wz,
                                  const float* __restrict__ Wr,
                                  const float* __restrict__ Wc) {
    long idx = (long)blockIdx.x * 256 + threadIdx.x;
    const long NSPLIT = 3L * HH * HH;
    if (idx < NSPLIT) {
        int g = (int)(idx / (HH * HH));
        int rem = (int)(idx % (HH * HH));
        int j = rem / HH, k = rem % HH;
        const float* Wg = (g == 0) ? Wz : (g == 1) ? Wr : Wc;
        float w = Wg[(long)j * KW + k];
        __nv_bfloat16 hi = __float2bfloat16(w);
        g_w[g][0][rem] = hi;
        g_w[g][1][rem] = __float2bfloat16(w - __bfloat162float(hi));
    } else {
        long r = idx - NSPLIT;
        if (r < 3L * VV * HH) {
            int g = (int)(r / (VV * HH));
            int rem = (int)(r % (VV * HH));
            int v = rem / HH, j = rem % HH;
            const float* Wg = (g == 0) ? Wz : (g == 1) ? Wr : Wc;
            float s = 0.f;
#pragma unroll
            for (int e = 0; e < EE; ++e)
                s += embed[v * EE + e] * Wg[(long)j * KW + HH + e];
            g_pre[g][v][j] = s;
        }
    }
}

// ---------------- cp.async staging ----------------
// phase1: 4 mats x 64 rows x 8 16B-cols = 2048 ops, 4/thread
static __device__ __forceinline__ void issue_stage1(
    uint32_t sbuf,
    const __nv_bfloat16* __restrict__ ahi, const __nv_bfloat16* __restrict__ alo,
    const __nv_bfloat16* __restrict__ bhi, const __nv_bfloat16* __restrict__ blo,
    int k0, int tid) {
#pragma unroll
    for (int i = 0; i < 4; ++i) {
        int u = tid + (i << 9);
        const __nv_bfloat16* base = (i == 0) ? ahi : (i == 1) ? alo : (i == 2) ? bhi : blo;
        int v = u & 511;
        int row = v >> 3, c = v & 7;
        const void* src = base + (long)row * HH + k0 + (c << 3);
        uint32_t dst = sbuf + (u >> 9) * MATSZ + row * 144 + (c << 4);
        asm volatile("cp.async.cg.shared.global [%0], [%1], 16;" :: "r"(dst), "l"(src));
    }
    asm volatile("cp.async.commit_group;" ::: "memory");
}

// phase2: both K-halves. A: 2 halves x 2 mats x 32 rows x 8 = 1024 ops;
// B: 2 x 2 x 64 x 8 = 2048 ops. total 3072, 6/thread.
static __device__ __forceinline__ void issue_stage2(
    uint32_t sbuf,
    const __nv_bfloat16* __restrict__ ahi, const __nv_bfloat16* __restrict__ alo,
    const __nv_bfloat16* __restrict__ bhi, const __nv_bfloat16* __restrict__ blo,
    int k0, int tid) {
#pragma unroll
    for (int i = 0; i < 2; ++i) {   // A ops
        int u = tid + (i << 9);
        int half = u >> 9, v = u & 511;
        int mat = v >> 8, w = v & 255;
        int row = w >> 3, c = w & 7;
        const __nv_bfloat16* base = mat ? alo : ahi;
        const void* src = base + (long)row * HH + half * 512 + k0 + (c << 3);
        uint32_t dst = sbuf + half * 9216 + mat * 4608 + row * 144 + (c << 4);
        asm volatile("cp.async.cg.shared.global [%0], [%1], 16;" :: "r"(dst), "l"(src));
    }
#pragma unroll
    for (int i = 0; i < 4; ++i) {   // B ops
        int u = tid + (i << 9);
        int half = u >> 10, v = u & 1023;
        int mat = v >> 9, w = v & 511;
        int row = w >> 3, c = w & 7;
        const __nv_bfloat16* base = mat ? blo : bhi;
        const void* src = base + (long)row * HH + half * 512 + k0 + (c << 3);
        uint32_t dst = sbuf + 18432 + half * 18432 + mat * MATSZ + row * 144 + (c << 4);
        asm volatile("cp.async.cg.shared.global [%0], [%1], 16;" :: "r"(dst), "l"(src));
    }
    asm volatile("cp.async.commit_group;" ::: "memory");
}

// ---------------- compute: one K=64 chunk, warp tile 16x16, 3 chains ------
static __device__ __forceinline__ void compute16(
    const char* Ah_, const char* Al_, const char* Bh_, const char* Bl_,
    int wm, int wn, FragC& ch, FragC& cm1, FragC& cm2) {
    const __nv_bfloat16* Ah = reinterpret_cast<const __nv_bfloat16*>(Ah_);
    const __nv_bfloat16* Al = reinterpret_cast<const __nv_bfloat16*>(Al_);
    const __nv_bfloat16* Bh = reinterpret_cast<const __nv_bfloat16*>(Bh_);
    const __nv_bfloat16* Bl = reinterpret_cast<const __nv_bfloat16*>(Bl_);
#pragma unroll
    for (int ks = 0; ks < 4; ++ks) {
        FragA ah, al;
        FragB bh, bl;
        wmma::load_matrix_sync(ah, Ah + (wm * 16) * LDMAB + ks * 16, LDMAB);
        wmma::load_matrix_sync(bh, Bh + (wn * 16) * LDMAB + ks * 16, LDMAB);
        wmma::load_matrix_sync(al, Al + (wm * 16) * LDMAB + ks * 16, LDMAB);
        wmma::load_matrix_sync(bl, Bl + (wn * 16) * LDMAB + ks * 16, LDMAB);
        wmma::mma_sync(ch, ah, bh, ch);
        wmma::mma_sync(cm1, ah, bl, cm1);
        wmma::mma_sync(cm2, al, bh, cm2);
    }
}

// ---------------- phase1 GEMM: 64x64x1024, 3-stage ----------------
static __device__ void run_gemm1(
    char* sm, uint32_t sbase,
    const __nv_bfloat16* __restrict__ ahi, const __nv_bfloat16* __restrict__ alo,
    const __nv_bfloat16* __restrict__ bhi, const __nv_bfloat16* __restrict__ blo,
    int tid, int wid, FragC& ch) {
    FragC cm1, cm2;
    wmma::fill_fragment(ch, 0.f);
    wmma::fill_fragment(cm1, 0.f);
    wmma::fill_fragment(cm2, 0.f);
    const int wm = wid & 3, wn = wid >> 2;

    issue_stage1(sbase + 1024, ahi, alo, bhi, blo, 0, tid);
    issue_stage1(sbase + 1024 + P1STRIDE, ahi, alo, bhi, blo, 64, tid);

#pragma unroll 1
    for (int c = 0; c < 16; ++c) {
        if (c < 14) asm volatile("cp.async.wait_group 1;" ::: "memory");
        else        asm volatile("cp.async.wait_group 0;" ::: "memory");
        __syncthreads();
        if (c < 14)
            issue_stage1(sbase + 1024 + ((c + 2) % 3) * P1STRIDE,
                         ahi, alo, bhi, blo, (c + 2) * 64, tid);
        const char* buf = sm + 1024 + (c % 3) * P1STRIDE;
        compute16(buf, buf + MATSZ, buf + 2 * MATSZ, buf + 3 * MATSZ, wm, wn, ch, cm1, cm2);
    }
#pragma unroll
    for (int i = 0; i < ch.num_elements; ++i)
        ch.x[i] += cm1.x[i] + cm2.x[i];
    __syncthreads();
}

// ---------------- phase2 GEMM: 32x64x1024 K-split, 2-stage ----------------
static __device__ void run_gemm2(
    char* sm, uint32_t sbase,
    const __nv_bfloat16* __restrict__ ahi, const __nv_bfloat16* __restrict__ alo,
    const __nv_bfloat16* __restrict__ bhi, const __nv_bfloat16* __restrict__ blo,
    int tid, int wid, FragC& ch) {
    FragC cm1, cm2;
    wmma::fill_fragment(ch, 0.f);
    wmma::fill_fragment(cm1, 0.f);
    wmma::fill_fragment(cm2, 0.f);
    const int khalf = wid >> 3;
    const int w8 = wid & 7;
    const int wm = w8 & 1, wn = w8 >> 1;

    issue_stage2(sbase + 1024, ahi, alo, bhi, blo, 0, tid);

#pragma unroll 1
    for (int c = 0; c < 8; ++c) {
        asm volatile("cp.async.wait_group 0;" ::: "memory");
        __syncthreads();
        if (c < 7)
            issue_stage2(sbase + 1024 + ((c + 1) & 1) * P2STRIDE,
                         ahi, alo, bhi, blo, (c + 1) * 64, tid);
        const char* buf = sm + 1024 + (c & 1) * P2STRIDE;
        const char* Ah = buf + khalf * 9216;
        const char* Bh = buf + 18432 + khalf * 18432;
        compute16(Ah, Ah + 4608, Bh, Bh + MATSZ, wm, wn, ch, cm1, cm2);
    }
#pragma unroll
    for (int i = 0; i < ch.num_elements; ++i)
        ch.x[i] += cm1.x[i] + cm2.x[i];
    __syncthreads();
}

// ---------------- main persistent kernel ----------------
__global__ void __launch_bounds__(NTHR, 1)
gru_tc(const int* __restrict__ x,
       const float* __restrict__ Wph,
       const float* __restrict__ bp,
       float* __restrict__ out) {
    extern __shared__ __align__(16) char smem[];
    const uint32_t sbase = smem_u32(smem);
    const int tid = threadIdx.x;
    const int wid = tid >> 5;
    const int lane = tid & 31;
    const int cta = blockIdx.x;

    for (int i = cta * NTHR + tid; i < BB * HH; i += NCTA * NTHR) {
        g_h[i] = 0.f;
        g_ha[0][i] = __float2bfloat16(0.f);
        g_ha[1][i] = __float2bfloat16(0.f);
    }
    grid_sync();

    // phase1: 128 tiles = 4 M-strips(64) x (16 z + 16 r) N-tiles(64)
    const int p1_bm = (cta & 3) << 6;
    const int p1_nt = cta >> 2;
    const int p1_gate = p1_nt >> 4;
    const int p1_jb = (p1_nt & 15) << 6;
    // phase2: 128 tiles = 8 M-strips(32) x 16 N-tiles(64)
    const int p2_bm = (cta & 7) << 5;
    const int p2_jb = (cta >> 3) << 6;

    float* sC = reinterpret_cast<float*>(smem + 1024);
    FragC ch;

    for (int t = 0; t < TT; ++t) {
        // ============ phase 1: z / r gates ============
        run_gemm1(smem, sbase,
                  &g_ha[0][p1_bm * HH], &g_ha[1][p1_bm * HH],
                  &g_w[p1_gate][0][p1_jb * HH], &g_w[p1_gate][1][p1_jb * HH],
                  tid, wid, ch);
        {
            const int wm = wid & 3, wn = wid >> 2;
            wmma::store_matrix_sync(sC + (wm * 16) * LDMC + wn * 16, ch, LDMC, wmma::mem_row_major);
        }
        __syncthreads();
        {
            const int er = tid >> 3;              // 0..63
            const int ecb = (tid & 7) << 3;       // 8 cols
            const int b = p1_bm + er;
            const int tok = x[b * TT + t];
            const float* __restrict__ pre = &g_pre[p1_gate][tok][p1_jb + ecb];
            const float* __restrict__ cr = sC + er * LDMC + ecb;
            if (p1_gate == 0) {
                float* __restrict__ dst = &g_z[b * HH + p1_jb + ecb];
#pragma unroll
                for (int q = 0; q < 2; ++q) {
                    float4 v = *reinterpret_cast<const float4*>(cr + q * 4);
                    float4 p = *reinterpret_cast<const float4*>(pre + q * 4);
                    float4 o;
                    o.x = sigf(v.x + p.x);
                    o.y = sigf(v.y + p.y);
                    o.z = sigf(v.z + p.z);
                    o.w = sigf(v.w + p.w);
                    *reinterpret_cast<float4*>(dst + q * 4) = o;
                }
            } else {
                const float* __restrict__ hrow = &g_h[b * HH + p1_jb + ecb];
                float hr[8];
#pragma unroll
                for (int q = 0; q < 2; ++q) {
                    float4 v = *reinterpret_cast<const float4*>(cr + q * 4);
                    float4 p = *reinterpret_cast<const float4*>(pre + q * 4);
                    float4 h4 = *reinterpret_cast<const float4*>(hrow + q * 4);
                    hr[q * 4 + 0] = sigf(v.x + p.x) * h4.x;
                    hr[q * 4 + 1] = sigf(v.y + p.y) * h4.y;
                    hr[q * 4 + 2] = sigf(v.z + p.z) * h4.z;
                    hr[q * 4 + 3] = sigf(v.w + p.w) * h4.w;
                }
                uint32_t phi[4], plo[4];
#pragma unroll
                for (int q = 0; q < 4; ++q) {
                    float a = hr[2 * q], bx = hr[2 * q + 1];
                    float ea = a - __bfloat162float(__float2bfloat16(a));
                    float eb = bx - __bfloat162float(__float2bfloat16(bx));
                    phi[q] = pack_bf2(a, bx);
                    plo[q] = pack_bf2(ea, eb);
                }
                *reinterpret_cast<uint4*>(&g_hra[0][b * HH + p1_jb + ecb]) =
                    make_uint4(phi[0], phi[1], phi[2], phi[3]);
                *reinterpret_cast<uint4*>(&g_hra[1][b * HH + p1_jb + ecb]) =
                    make_uint4(plo[0], plo[1], plo[2], plo[3]);
            }
        }
        grid_sync();

        // ============ phase 2: candidate + state update ============
        run_gemm2(smem, sbase,
                  &g_hra[0][p2_bm * HH], &g_hra[1][p2_bm * HH],
                  &g_w[2][0][p2_jb * HH], &g_w[2][1][p2_jb * HH],
                  tid, wid, ch);
        {
            const int khalf = wid >> 3;
            const int w8 = wid & 7;
            const int wm = w8 & 1, wn = w8 >> 1;
            wmma::store_matrix_sync(sC + khalf * (32 * LDMC) + (wm * 16) * LDMC + wn * 16,
                                    ch, LDMC, wmma::mem_row_major);
        }
        __syncthreads();
        {
            const int er = tid >> 4;              // 0..31
            const int ecb = (tid & 15) << 2;      // 4 cols
            const int b = p2_bm + er;
            const int tok = x[b * TT + t];
            const float* __restrict__ pre = &g_pre[2][tok][p2_jb + ecb];
            const float* __restrict__ cr0 = sC + er * LDMC + ecb;
            const float* __restrict__ cr1 = cr0 + 32 * LDMC;
            float* __restrict__ hrow = &g_h[b * HH + p2_jb + ecb];
            const float* __restrict__ zrow = &g_z[b * HH + p2_jb + ecb];
            float4 v0 = *reinterpret_cast<const float4*>(cr0);
            float4 v1 = *reinterpret_cast<const float4*>(cr1);
            float4 p = *reinterpret_cast<const float4*>(pre);
            float4 h4 = *reinterpret_cast<const float4*>(hrow);
            float4 z4 = *reinterpret_cast<const float4*>(zrow);
            float hn[4];
            hn[0] = h4.x + z4.x * (fast_tanh(v0.x + v1.x + p.x) - h4.x);
            hn[1] = h4.y + z4.y * (fast_tanh(v0.y + v1.y + p.y) - h4.y);
            hn[2] = h4.z + z4.z * (fast_tanh(v0.z + v1.z + p.z) - h4.z);
            hn[3] = h4.w + z4.w * (fast_tanh(v0.w + v1.w + p.w) - h4.w);
            *reinterpret_cast<float4*>(hrow) = make_float4(hn[0], hn[1], hn[2], hn[3]);
            uint32_t phi[2], plo[2];
#pragma unroll
            for (int q = 0; q < 2; ++q) {
                float a = hn[2 * q], bx = hn[2 * q + 1];
                float ea = a - __bfloat162float(__float2bfloat16(a));
                float eb = bx - __bfloat162float(__float2bfloat16(bx));
                phi[q] = pack_bf2(a, bx);
                plo[q] = pack_bf2(ea, eb);
            }
            *reinterpret_cast<uint2*>(&g_ha[0][b * HH + p2_jb + ecb]) = make_uint2(phi[0], phi[1]);
            *reinterpret_cast<uint2*>(&g_ha[1][b * HH + p2_jb + ecb]) = make_uint2(plo[0], plo[1]);
        }
        grid_sync();
    }

    // ============ output projection ============
    const int warpId = (cta << 4) + wid;
    const int nWarps = NCTA << 4;
    for (int oc = warpId; oc < BB * CC; oc += nWarps) {
        const int b = oc / CC;
        const int c = oc - b * CC;
        const float* hrow = &g_h[b * HH];
        const float* wrow = &Wph[c * HH];
        float s = 0.f;
        for (int j = lane; j < HH; j += 32)
            s += hrow[j] * wrow[j];
#pragma unroll
        for (int off = 16; off; off >>= 1)
            s += __shfl_xor_sync(0xffffffffu, s, off);
        if (lane == 0) out[oc] = s + bp[c];
    }
}

// ---------------- launch ----------------
extern "C" void kernel_launch(void* const* d_in, const int* in_sizes, int n_in,
                              void* d_out, int out_size) {
    const int*   x     = (const int*)d_in[0];
    const float* embed = (const float*)d_in[1];
    const float* Wz    = (const float*)d_in[2];
    const float* Wr    = (const float*)d_in[3];
    const float* Wc    = (const float*)d_in[4];
    const float* Wph   = (const float*)d_in[5];
    const float* bp    = (const float*)d_in[6];
    float* out = (float*)d_out;

    cudaFuncSetAttribute(gru_tc, cudaFuncAttributeMaxDynamicSharedMemorySize, SMEM_TOTAL);

    const long total = 3L * HH * HH + 3L * VV * HH;
    precompute_kernel<<<(unsigned)((total + 255) / 256), 256>>>(embed, Wz, Wr, Wc);
    gru_tc<<<NCTA, NTHR, SMEM_TOTAL>>>(x, Wph, bp, out);
}

// round 8
// speedup vs baseline: 2.7705x; 1.0686x over previous
#include <cuda_runtime.h>
#include <cuda_bf16.h>
#include <mma.h>
#include <cstdint>
#include <math.h>

using namespace nvcuda;

#define BB 256
#define TT 512
#define VV 10
#define EE 10
#define HH 1024
#define CC 10
#define KW 1034
#define NCTA 128
#define NTHR 512

// ---------------- device scratch ----------------
__device__ float g_h[BB * HH];
__device__ float g_z[BB * HH];
__device__ __nv_bfloat16 g_ha[2][BB * HH];    // h hi/lo   (phase1 A)
__device__ __nv_bfloat16 g_hra[2][BB * HH];   // h*r hi/lo (phase2 A)
__device__ __nv_bfloat16 g_w[3][2][HH * HH];  // weight splits, K-major [j*HH+k]
__device__ float g_pre[3][VV][HH];            // x-path tables
__device__ unsigned g_count;
__device__ volatile unsigned g_phase;

// smem:
//  [0,1024)                 pad
//  [1024, 1024+3*P1STRIDE)  staging stages (phase1 uses P1STRIDE, phase2 P2STRIDE; both 3-deep)
//  [CBASE, CBASE+69632)     C partials (phase1: 4 x 64x68 f32; phase2: 4 x 32x68 f32)
#define P1STRIDE 36864   // Ahi 64x144B | Alo | Bhi | Blo
#define P2STRIDE 27648   // Ahi 32x144B | Alo | Bhi 64x144B | Blo
#define MATSZ    9216
#define LDMAB    72
#define LDMC     68
#define CBASE    (1024 + 3 * P1STRIDE)
#define SMEM_TOTAL (CBASE + 69632)

typedef wmma::fragment<wmma::accumulator, 16, 16, 16, float> FragC;
typedef wmma::fragment<wmma::matrix_a, 16, 16, 16, __nv_bfloat16, wmma::row_major> FragA;
typedef wmma::fragment<wmma::matrix_b, 16, 16, 16, __nv_bfloat16, wmma::col_major> FragB;

// ---------------- math ----------------
static __device__ __forceinline__ float sigf(float v) {
    return __fdividef(1.f, 1.f + __expf(-v));
}
static __device__ __forceinline__ float fast_tanh(float v) {
    v = fminf(fmaxf(v, -15.f), 15.f);
    float e = __expf(-2.f * v);
    return __fdividef(1.f - e, 1.f + e);
}
static __device__ __forceinline__ uint32_t pack_bf2(float a, float b) {
    __nv_bfloat16 x = __float2bfloat16(a), y = __float2bfloat16(b);
    return ((uint32_t)__bfloat16_as_ushort(y) << 16) | (uint32_t)__bfloat16_as_ushort(x);
}
static __device__ __forceinline__ uint32_t smem_u32(const void* p) {
    uint32_t a;
    asm("{ .reg .u64 t; cvta.to.shared.u64 t, %1; cvt.u32.u64 %0, t; }" : "=r"(a) : "l"(p));
    return a;
}

// ---------------- grid barrier ----------------
static __device__ __forceinline__ void grid_sync() {
    __syncthreads();
    if (threadIdx.x == 0) {
        __threadfence();
        unsigned ph = g_phase;
        if (atomicAdd(&g_count, 1u) == gridDim.x - 1u) {
            g_count = 0u;
            __threadfence();
            g_phase = ph + 1u;
        } else {
            while (g_phase == ph) { __nanosleep(32); }
        }
        __threadfence();
    }
    __syncthreads();
}

// ---------------- precompute ----------------
__global__ void precompute_kernel(const float* __restrict__ embed,
                                  const float* __restrict__ Wz,
                                  const float* __restrict__ Wr,
                                  const float* __restrict__ Wc) {
    long idx = (long)blockIdx.x * 256 + threadIdx.x;
    const long NSPLIT = 3L * HH * HH;
    if (idx < NSPLIT) {
        int g = (int)(idx / (HH * HH));
        int rem = (int)(idx % (HH * HH));
        int j = rem / HH, k = rem % HH;
        const float* Wg = (g == 0) ? Wz : (g == 1) ? Wr : Wc;
        float w = Wg[(long)j * KW + k];
        __nv_bfloat16 hi = __float2bfloat16(w);
        g_w[g][0][rem] = hi;
        g_w[g][1][rem] = __float2bfloat16(w - __bfloat162float(hi));
    } else {
        long r = idx - NSPLIT;
        if (r < 3L * VV * HH) {
            int g = (int)(r / (VV * HH));
            int rem = (int)(r % (VV * HH));
            int v = rem / HH, j = rem % HH;
            const float* Wg = (g == 0) ? Wz : (g == 1) ? Wr : Wc;
            float s = 0.f;
#pragma unroll
            for (int e = 0; e < EE; ++e)
                s += embed[v * EE + e] * Wg[(long)j * KW + HH + e];
            g_pre[g][v][j] = s;
        }
    }
}

// ---------------- cp.async staging ----------------
// phase1: Ahi/Alo 64 rows + Bhi/Blo 64 rows, 4 ops/thread
static __device__ __forceinline__ void issue_stage1(
    uint32_t sbuf,
    const __nv_bfloat16* __restrict__ ahi, const __nv_bfloat16* __restrict__ alo,
    const __nv_bfloat16* __restrict__ bhi, const __nv_bfloat16* __restrict__ blo,
    int k0, int tid) {
#pragma unroll
    for (int i = 0; i < 4; ++i) {
        const __nv_bfloat16* base = (i == 0) ? ahi : (i == 1) ? alo : (i == 2) ? bhi : blo;
        int row = tid >> 3, c = tid & 7;
        const void* src = base + (long)row * HH + k0 + (c << 3);
        uint32_t dst = sbuf + i * MATSZ + row * 144 + (c << 4);
        asm volatile("cp.async.cg.shared.global [%0], [%1], 16;" :: "r"(dst), "l"(src));
    }
    asm volatile("cp.async.commit_group;" ::: "memory");
}

// phase2: Ahi/Alo 32 rows (1 op/thread), Bhi/Blo 64 rows (2 ops/thread)
static __device__ __forceinline__ void issue_stage2(
    uint32_t sbuf,
    const __nv_bfloat16* __restrict__ ahi, const __nv_bfloat16* __restrict__ alo,
    const __nv_bfloat16* __restrict__ bhi, const __nv_bfloat16* __restrict__ blo,
    int k0, int tid) {
    {   // A: 2 mats x 32 rows x 8
        int mat = tid >> 8, v = tid & 255;
        int row = v >> 3, c = v & 7;
        const __nv_bfloat16* base = mat ? alo : ahi;
        const void* src = base + (long)row * HH + k0 + (c << 3);
        uint32_t dst = sbuf + mat * 4608 + row * 144 + (c << 4);
        asm volatile("cp.async.cg.shared.global [%0], [%1], 16;" :: "r"(dst), "l"(src));
    }
#pragma unroll
    for (int i = 0; i < 2; ++i) {   // B: 2 mats x 64 rows x 8
        int u = tid + (i << 9);
        int mat = u >> 9, v = u & 511;
        int row = v >> 3, c = v & 7;
        const __nv_bfloat16* base = mat ? blo : bhi;
        const void* src = base + (long)row * HH + k0 + (c << 3);
        uint32_t dst = sbuf + 9216 + mat * MATSZ + row * 144 + (c << 4);
        asm volatile("cp.async.cg.shared.global [%0], [%1], 16;" :: "r"(dst), "l"(src));
    }
    asm volatile("cp.async.commit_group;" ::: "memory");
}

// ---------------- phase1 compute: warp tile 32x32, one kstep ----------------
static __device__ __forceinline__ void compute_p1(
    const char* buf, int grp, int wm, int wn,
    FragC& c00, FragC& c01, FragC& c10, FragC& c11) {
    const __nv_bfloat16* Ah = reinterpret_cast<const __nv_bfloat16*>(buf);
    const __nv_bfloat16* Al = reinterpret_cast<const __nv_bfloat16*>(buf + MATSZ);
    const __nv_bfloat16* Bh = reinterpret_cast<const __nv_bfloat16*>(buf + 2 * MATSZ);
    const __nv_bfloat16* Bl = reinterpret_cast<const __nv_bfloat16*>(buf + 3 * MATSZ);
    const int ko = grp << 4;
    FragA ah0, ah1, al0, al1;
    FragB bh0, bh1, bl0, bl1;
    wmma::load_matrix_sync(ah0, Ah + (wm * 32) * LDMAB + ko, LDMAB);
    wmma::load_matrix_sync(ah1, Ah + (wm * 32 + 16) * LDMAB + ko, LDMAB);
    wmma::load_matrix_sync(bh0, Bh + (wn * 32) * LDMAB + ko, LDMAB);
    wmma::load_matrix_sync(bh1, Bh + (wn * 32 + 16) * LDMAB + ko, LDMAB);
    wmma::mma_sync(c00, ah0, bh0, c00);
    wmma::mma_sync(c01, ah0, bh1, c01);
    wmma::mma_sync(c10, ah1, bh0, c10);
    wmma::mma_sync(c11, ah1, bh1, c11);
    wmma::load_matrix_sync(bl0, Bl + (wn * 32) * LDMAB + ko, LDMAB);
    wmma::load_matrix_sync(bl1, Bl + (wn * 32 + 16) * LDMAB + ko, LDMAB);
    wmma::mma_sync(c00, ah0, bl0, c00);
    wmma::mma_sync(c01, ah0, bl1, c01);
    wmma::mma_sync(c10, ah1, bl0, c10);
    wmma::mma_sync(c11, ah1, bl1, c11);
    wmma::load_matrix_sync(al0, Al + (wm * 32) * LDMAB + ko, LDMAB);
    wmma::load_matrix_sync(al1, Al + (wm * 32 + 16) * LDMAB + ko, LDMAB);
    wmma::mma_sync(c00, al0, bh0, c00);
    wmma::mma_sync(c01, al0, bh1, c01);
    wmma::mma_sync(c10, al1, bh0, c10);
    wmma::mma_sync(c11, al1, bh1, c11);
}

// ---------------- phase2 compute: warp tile 16x32, one kstep ----------------
static __device__ __forceinline__ void compute_p2(
    const char* buf, int grp, int wm, int wn, FragC& c0, FragC& c1) {
    const __nv_bfloat16* Ah = reinterpret_cast<const __nv_bfloat16*>(buf);
    const __nv_bfloat16* Al = reinterpret_cast<const __nv_bfloat16*>(buf + 4608);
    const __nv_bfloat16* Bh = reinterpret_cast<const __nv_bfloat16*>(buf + 9216);
    const __nv_bfloat16* Bl = reinterpret_cast<const __nv_bfloat16*>(buf + 9216 + MATSZ);
    const int ko = grp << 4;
    FragA ah, al;
    FragB bh0, bh1, bl0, bl1;
    wmma::load_matrix_sync(ah, Ah + (wm * 16) * LDMAB + ko, LDMAB);
    wmma::load_matrix_sync(bh0, Bh + (wn * 32) * LDMAB + ko, LDMAB);
    wmma::load_matrix_sync(bh1, Bh + (wn * 32 + 16) * LDMAB + ko, LDMAB);
    wmma::mma_sync(c0, ah, bh0, c0);
    wmma::mma_sync(c1, ah, bh1, c1);
    wmma::load_matrix_sync(bl0, Bl + (wn * 32) * LDMAB + ko, LDMAB);
    wmma::load_matrix_sync(bl1, Bl + (wn * 32 + 16) * LDMAB + ko, LDMAB);
    wmma::mma_sync(c0, ah, bl0, c0);
    wmma::mma_sync(c1, ah, bl1, c1);
    wmma::load_matrix_sync(al, Al + (wm * 16) * LDMAB + ko, LDMAB);
    wmma::mma_sync(c0, al, bh0, c0);
    wmma::mma_sync(c1, al, bh1, c1);
}

// ---------------- phase1 GEMM: 64x64x1024, 3-stage, K-grouped -------------
static __device__ void run_gemm1(
    char* sm, uint32_t sbase,
    const __nv_bfloat16* __restrict__ ahi, const __nv_bfloat16* __restrict__ alo,
    const __nv_bfloat16* __restrict__ bhi, const __nv_bfloat16* __restrict__ blo,
    int tid, int grp, int wm, int wn) {
    FragC c00, c01, c10, c11;
    wmma::fill_fragment(c00, 0.f);
    wmma::fill_fragment(c01, 0.f);
    wmma::fill_fragment(c10, 0.f);
    wmma::fill_fragment(c11, 0.f);

    issue_stage1(sbase + 1024, ahi, alo, bhi, blo, 0, tid);
    issue_stage1(sbase + 1024 + P1STRIDE, ahi, alo, bhi, blo, 64, tid);

#pragma unroll 1
    for (int c = 0; c < 16; ++c) {
        if (c < 14) asm volatile("cp.async.wait_group 1;" ::: "memory");
        else        asm volatile("cp.async.wait_group 0;" ::: "memory");
        __syncthreads();
        if (c < 14)
            issue_stage1(sbase + 1024 + ((c + 2) % 3) * P1STRIDE,
                         ahi, alo, bhi, blo, (c + 2) * 64, tid);
        compute_p1(sm + 1024 + (c % 3) * P1STRIDE, grp, wm, wn, c00, c01, c10, c11);
    }
    float* sCg = reinterpret_cast<float*>(sm + CBASE) + grp * (64 * LDMC);
    wmma::store_matrix_sync(sCg + (wm * 32) * LDMC + wn * 32, c00, LDMC, wmma::mem_row_major);
    wmma::store_matrix_sync(sCg + (wm * 32) * LDMC + wn * 32 + 16, c01, LDMC, wmma::mem_row_major);
    wmma::store_matrix_sync(sCg + (wm * 32 + 16) * LDMC + wn * 32, c10, LDMC, wmma::mem_row_major);
    wmma::store_matrix_sync(sCg + (wm * 32 + 16) * LDMC + wn * 32 + 16, c11, LDMC, wmma::mem_row_major);
    __syncthreads();
}

// ---------------- phase2 GEMM: 32x64x1024, 3-stage, K-grouped -------------
static __device__ void run_gemm2(
    char* sm, uint32_t sbase,
    const __nv_bfloat16* __restrict__ ahi, const __nv_bfloat16* __restrict__ alo,
    const __nv_bfloat16* __restrict__ bhi, const __nv_bfloat16* __restrict__ blo,
    int tid, int grp, int wm, int wn) {
    FragC c0, c1;
    wmma::fill_fragment(c0, 0.f);
    wmma::fill_fragment(c1, 0.f);

    issue_stage2(sbase + 1024, ahi, alo, bhi, blo, 0, tid);
    issue_stage2(sbase + 1024 + P2STRIDE, ahi, alo, bhi, blo, 64, tid);

#pragma unroll 1
    for (int c = 0; c < 16; ++c) {
        if (c < 14) asm volatile("cp.async.wait_group 1;" ::: "memory");
        else        asm volatile("cp.async.wait_group 0;" ::: "memory");
        __syncthreads();
        if (c < 14)
            issue_stage2(sbase + 1024 + ((c + 2) % 3) * P2STRIDE,
                         ahi, alo, bhi, blo, (c + 2) * 64, tid);
        compute_p2(sm + 1024 + (c % 3) * P2STRIDE, grp, wm, wn, c0, c1);
    }
    float* sCg = reinterpret_cast<float*>(sm + CBASE) + grp * (32 * LDMC);
    wmma::store_matrix_sync(sCg + (wm * 16) * LDMC + wn * 32, c0, LDMC, wmma::mem_row_major);
    wmma::store_matrix_sync(sCg + (wm * 16) * LDMC + wn * 32 + 16, c1, LDMC, wmma::mem_row_major);
    __syncthreads();
}

// ---------------- main persistent kernel ----------------
__global__ void __launch_bounds__(NTHR, 1)
gru_tc(const int* __restrict__ x,
       const float* __restrict__ Wph,
       const float* __restrict__ bp,
       float* __restrict__ out) {
    extern __shared__ __align__(16) char smem[];
    const uint32_t sbase = smem_u32(smem);
    const int tid = threadIdx.x;
    const int wid = tid >> 5;
    const int lane = tid & 31;
    const int cta = blockIdx.x;
    const int grp = wid >> 2;            // K group 0..3
    const int wpos = wid & 3;
    const int wm = wpos & 1, wn = wpos >> 1;

    for (int i = cta * NTHR + tid; i < BB * HH; i += NCTA * NTHR) {
        g_h[i] = 0.f;
        g_ha[0][i] = __float2bfloat16(0.f);
        g_ha[1][i] = __float2bfloat16(0.f);
    }
    grid_sync();

    // phase1: 128 tiles = 4 M-strips(64) x (16 z + 16 r) N-tiles(64)
    const int p1_bm = (cta & 3) << 6;
    const int p1_nt = cta >> 2;
    const int p1_gate = p1_nt >> 4;
    const int p1_jb = (p1_nt & 15) << 6;
    // phase2: 128 tiles = 8 M-strips(32) x 16 N-tiles(64)
    const int p2_bm = (cta & 7) << 5;
    const int p2_jb = (cta >> 3) << 6;

    const float* sC = reinterpret_cast<const float*>(smem + CBASE);

    for (int t = 0; t < TT; ++t) {
        // ============ phase 1: z / r gates ============
        run_gemm1(smem, sbase,
                  &g_ha[0][p1_bm * HH], &g_ha[1][p1_bm * HH],
                  &g_w[p1_gate][0][p1_jb * HH], &g_w[p1_gate][1][p1_jb * HH],
                  tid, grp, wm, wn);
        {
            const int er = tid >> 3;              // 0..63
            const int ecb = (tid & 7) << 3;       // 8 cols
            const float* cr = sC + er * LDMC + ecb;
            float v[8];
            {
                float4 a0 = *reinterpret_cast<const float4*>(cr);
                float4 a1 = *reinterpret_cast<const float4*>(cr + 4);
#pragma unroll
                for (int g = 1; g < 4; ++g) {
                    const float* crg = cr + g * (64 * LDMC);
                    float4 b0 = *reinterpret_cast<const float4*>(crg);
                    float4 b1 = *reinterpret_cast<const float4*>(crg + 4);
                    a0.x += b0.x; a0.y += b0.y; a0.z += b0.z; a0.w += b0.w;
                    a1.x += b1.x; a1.y += b1.y; a1.z += b1.z; a1.w += b1.w;
                }
                v[0] = a0.x; v[1] = a0.y; v[2] = a0.z; v[3] = a0.w;
                v[4] = a1.x; v[5] = a1.y; v[6] = a1.z; v[7] = a1.w;
            }
            const int b = p1_bm + er;
            const int tok = x[b * TT + t];
            const float* __restrict__ pre = &g_pre[p1_gate][tok][p1_jb + ecb];
            if (p1_gate == 0) {
                float* __restrict__ dst = &g_z[b * HH + p1_jb + ecb];
#pragma unroll
                for (int q = 0; q < 2; ++q) {
                    float4 p = *reinterpret_cast<const float4*>(pre + q * 4);
                    float4 o;
                    o.x = sigf(v[q * 4 + 0] + p.x);
                    o.y = sigf(v[q * 4 + 1] + p.y);
                    o.z = sigf(v[q * 4 + 2] + p.z);
                    o.w = sigf(v[q * 4 + 3] + p.w);
                    *reinterpret_cast<float4*>(dst + q * 4) = o;
                }
            } else {
                const float* __restrict__ hrow = &g_h[b * HH + p1_jb + ecb];
                float hr[8];
#pragma unroll
                for (int q = 0; q < 2; ++q) {
                    float4 p = *reinterpret_cast<const float4*>(pre + q * 4);
                    float4 h4 = *reinterpret_cast<const float4*>(hrow + q * 4);
                    hr[q * 4 + 0] = sigf(v[q * 4 + 0] + p.x) * h4.x;
                    hr[q * 4 + 1] = sigf(v[q * 4 + 1] + p.y) * h4.y;
                    hr[q * 4 + 2] = sigf(v[q * 4 + 2] + p.z) * h4.z;
                    hr[q * 4 + 3] = sigf(v[q * 4 + 3] + p.w) * h4.w;
                }
                uint32_t phi[4], plo[4];
#pragma unroll
                for (int q = 0; q < 4; ++q) {
                    float a = hr[2 * q], bx = hr[2 * q + 1];
                    float ea = a - __bfloat162float(__float2bfloat16(a));
                    float eb = bx - __bfloat162float(__float2bfloat16(bx));
                    phi[q] = pack_bf2(a, bx);
                    plo[q] = pack_bf2(ea, eb);
                }
                *reinterpret_cast<uint4*>(&g_hra[0][b * HH + p1_jb + ecb]) =
                    make_uint4(phi[0], phi[1], phi[2], phi[3]);
                *reinterpret_cast<uint4*>(&g_hra[1][b * HH + p1_jb + ecb]) =
                    make_uint4(plo[0], plo[1], plo[2], plo[3]);
            }
        }
        grid_sync();

        // ============ phase 2: candidate + state update ============
        run_gemm2(smem, sbase,
                  &g_hra[0][p2_bm * HH], &g_hra[1][p2_bm * HH],
                  &g_w[2][0][p2_jb * HH], &g_w[2][1][p2_jb * HH],
                  tid, grp, wm, wn);
        {
            const int er = tid >> 4;              // 0..31
            const int ecb = (tid & 15) << 2;      // 4 cols
            const float* cr = sC + er * LDMC + ecb;
            float4 v = *reinterpret_cast<const float4*>(cr);
#pragma unroll
            for (int g = 1; g < 4; ++g) {
                float4 bq = *reinterpret_cast<const float4*>(cr + g * (32 * LDMC));
                v.x += bq.x; v.y += bq.y; v.z += bq.z; v.w += bq.w;
            }
            const int b = p2_bm + er;
            const int tok = x[b * TT + t];
            const float* __restrict__ pre = &g_pre[2][tok][p2_jb + ecb];
            float* __restrict__ hrow = &g_h[b * HH + p2_jb + ecb];
            const float* __restrict__ zrow = &g_z[b * HH + p2_jb + ecb];
            float4 p = *reinterpret_cast<const float4*>(pre);
            float4 h4 = *reinterpret_cast<const float4*>(hrow);
            float4 z4 = *reinterpret_cast<const float4*>(zrow);
            float hn[4];
            hn[0] = h4.x + z4.x * (fast_tanh(v.x + p.x) - h4.x);
            hn[1] = h4.y + z4.y * (fast_tanh(v.y + p.y) - h4.y);
            hn[2] = h4.z + z4.z * (fast_tanh(v.z + p.z) - h4.z);
            hn[3] = h4.w + z4.w * (fast_tanh(v.w + p.w) - h4.w);
            *reinterpret_cast<float4*>(hrow) = make_float4(hn[0], hn[1], hn[2], hn[3]);
            uint32_t phi[2], plo[2];
#pragma unroll
            for (int q = 0; q < 2; ++q) {
                float a = hn[2 * q], bx = hn[2 * q + 1];
                float ea = a - __bfloat162float(__float2bfloat16(a));
                float eb = bx - __bfloat162float(__float2bfloat16(bx));
                phi[q] = pack_bf2(a, bx);
                plo[q] = pack_bf2(ea, eb);
            }
            *reinterpret_cast<uint2*>(&g_ha[0][b * HH + p2_jb + ecb]) = make_uint2(phi[0], phi[1]);
            *reinterpret_cast<uint2*>(&g_ha[1][b * HH + p2_jb + ecb]) = make_uint2(plo[0], plo[1]);
        }
        grid_sync();
    }

    // ============ output projection ============
    const int warpId = (cta << 4) + wid;
    const int nWarps = NCTA << 4;
    for (int oc = warpId; oc < BB * CC; oc += nWarps) {
        const int b = oc / CC;
        const int c = oc - b * CC;
        const float* hrow = &g_h[b * HH];
        const float* wrow = &Wph[c * HH];
        float s = 0.f;
        for (int j = lane; j < HH; j += 32)
            s += hrow[j] * wrow[j];
#pragma unroll
        for (int off = 16; off; off >>= 1)
            s += __shfl_xor_sync(0xffffffffu, s, off);
        if (lane == 0) out[oc] = s + bp[c];
    }
}

// ---------------- launch ----------------
extern "C" void kernel_launch(void* const* d_in, const int* in_sizes, int n_in,
                              void* d_out, int out_size) {
    const int*   x     = (const int*)d_in[0];
    const float* embed = (const float*)d_in[1];
    const float* Wz    = (const float*)d_in[2];
    const float* Wr    = (const float*)d_in[3];
    const float* Wc    = (const float*)d_in[4];
    const float* Wph   = (const float*)d_in[5];
    const float* bp    = (const float*)d_in[6];
    float* out = (float*)d_out;

    cudaFuncSetAttribute(gru_tc, cudaFuncAttributeMaxDynamicSharedMemorySize, SMEM_TOTAL);

    const long total = 3L * HH * HH + 3L * VV * HH;
    precompute_kernel<<<(unsigned)((total + 255) / 256), 256>>>(embed, Wz, Wr, Wc);
    gru_tc<<<NCTA, NTHR, SMEM_TOTAL>>>(x, Wph, bp, out);
}

// round 9
// speedup vs baseline: 3.0202x; 1.0901x over previous
#include <cuda_runtime.h>
#include <cuda_bf16.h>
#include <mma.h>
#include <cstdint>
#include <math.h>

using namespace nvcuda;

#define BB 256
#define TT 512
#define VV 10
#define EE 10
#define HH 1024
#define CC 10
#define KW 1034
#define NCTA 128
#define NTHR 512

// ---------------- device scratch ----------------
__device__ float g_h[BB * HH];
__device__ float g_z[BB * HH];
__device__ __nv_bfloat16 g_ha[2][BB * HH];    // h hi/lo   (phase1 A)
__device__ __nv_bfloat16 g_hra[2][BB * HH];   // h*r hi/lo (phase2 A)
__device__ __nv_bfloat16 g_w[3][2][HH * HH];  // weight splits, K-major [j*HH+k]
__device__ float g_pre[3][VV][HH];            // x-path tables
__device__ unsigned g_count;
__device__ volatile unsigned g_phase;

// smem:
//  [0,1024)                     pad
//  [1024, 1024+2*P1CH)          2 stages of K=128 chunks
//  [CBASE, CBASE+69632)         C partials (phase1: 4 x 64x68 f32)
// phase1 K=64 sub-block: Ahi 64x144B | Alo | Bhi | Blo  (36864B); chunk = 2 sub-blocks
// phase2 K=64 sub-block: Ahi 32x144B | Alo | Bhi 64x144B | Blo (27648B); chunk = 2
#define P1SUB  36864
#define P1CH   73728
#define P2SUB  27648
#define P2CH   55296
#define MATSZ  9216
#define LDMAB  72
#define LDMC   68
#define CBASE  (1024 + 2 * P1CH)
#define SMEM_TOTAL (CBASE + 69632)

typedef wmma::fragment<wmma::accumulator, 16, 16, 16, float> FragC;
typedef wmma::fragment<wmma::matrix_a, 16, 16, 16, __nv_bfloat16, wmma::row_major> FragA;
typedef wmma::fragment<wmma::matrix_b, 16, 16, 16, __nv_bfloat16, wmma::col_major> FragB;

// ---------------- math ----------------
static __device__ __forceinline__ float sigf(float v) {
    return __fdividef(1.f, 1.f + __expf(-v));
}
static __device__ __forceinline__ float fast_tanh(float v) {
    v = fminf(fmaxf(v, -15.f), 15.f);
    float e = __expf(-2.f * v);
    return __fdividef(1.f - e, 1.f + e);
}
static __device__ __forceinline__ uint32_t pack_bf2(float a, float b) {
    __nv_bfloat16 x = __float2bfloat16(a), y = __float2bfloat16(b);
    return ((uint32_t)__bfloat16_as_ushort(y) << 16) | (uint32_t)__bfloat16_as_ushort(x);
}
static __device__ __forceinline__ uint32_t smem_u32(const void* p) {
    uint32_t a;
    asm("{ .reg .u64 t; cvta.to.shared.u64 t, %1; cvt.u32.u64 %0, t; }" : "=r"(a) : "l"(p));
    return a;
}

// ---------------- grid barrier ----------------
static __device__ __forceinline__ void grid_sync() {
    __syncthreads();
    if (threadIdx.x == 0) {
        __threadfence();
        unsigned ph = g_phase;
        if (atomicAdd(&g_count, 1u) == gridDim.x - 1u) {
            g_count = 0u;
            __threadfence();
            g_phase = ph + 1u;
        } else {
            while (g_phase == ph) { __nanosleep(32); }
        }
        __threadfence();
    }
    __syncthreads();
}

// ---------------- precompute ----------------
__global__ void precompute_kernel(const float* __restrict__ embed,
                                  const float* __restrict__ Wz,
                                  const float* __restrict__ Wr,
                                  const float* __restrict__ Wc) {
    long idx = (long)blockIdx.x * 256 + threadIdx.x;
    const long NSPLIT = 3L * HH * HH;
    if (idx < NSPLIT) {
        int g = (int)(idx / (HH * HH));
        int rem = (int)(idx % (HH * HH));
        int j = rem / HH, k = rem % HH;
        const float* Wg = (g == 0) ? Wz : (g == 1) ? Wr : Wc;
        float w = Wg[(long)j * KW + k];
        __nv_bfloat16 hi = __float2bfloat16(w);
        g_w[g][0][rem] = hi;
        g_w[g][1][rem] = __float2bfloat16(w - __bfloat162float(hi));
    } else {
        long r = idx - NSPLIT;
        if (r < 3L * VV * HH) {
            int g = (int)(r / (VV * HH));
            int rem = (int)(r % (VV * HH));
            int v = rem / HH, j = rem % HH;
            const float* Wg = (g == 0) ? Wz : (g == 1) ? Wr : Wc;
            float s = 0.f;
#pragma unroll
            for (int e = 0; e < EE; ++e)
                s += embed[v * EE + e] * Wg[(long)j * KW + HH + e];
            g_pre[g][v][j] = s;
        }
    }
}

// ---------------- cp.async staging (one K=64 sub-block) ----------------
static __device__ __forceinline__ void issue_sub1(
    uint32_t sbuf,
    const __nv_bfloat16* __restrict__ ahi, const __nv_bfloat16* __restrict__ alo,
    const __nv_bfloat16* __restrict__ bhi, const __nv_bfloat16* __restrict__ blo,
    int k0, int tid) {
#pragma unroll
    for (int i = 0; i < 4; ++i) {
        const __nv_bfloat16* base = (i == 0) ? ahi : (i == 1) ? alo : (i == 2) ? bhi : blo;
        int row = tid >> 3, c = tid & 7;
        const void* src = base + (long)row * HH + k0 + (c << 3);
        uint32_t dst = sbuf + i * MATSZ + row * 144 + (c << 4);
        asm volatile("cp.async.cg.shared.global [%0], [%1], 16;" :: "r"(dst), "l"(src));
    }
}
static __device__ __forceinline__ void issue_chunk1(
    uint32_t sbuf,
    const __nv_bfloat16* __restrict__ ahi, const __nv_bfloat16* __restrict__ alo,
    const __nv_bfloat16* __restrict__ bhi, const __nv_bfloat16* __restrict__ blo,
    int k0, int tid) {
    issue_sub1(sbuf, ahi, alo, bhi, blo, k0, tid);
    issue_sub1(sbuf + P1SUB, ahi, alo, bhi, blo, k0 + 64, tid);
    asm volatile("cp.async.commit_group;" ::: "memory");
}

static __device__ __forceinline__ void issue_sub2(
    uint32_t sbuf,
    const __nv_bfloat16* __restrict__ ahi, const __nv_bfloat16* __restrict__ alo,
    const __nv_bfloat16* __restrict__ bhi, const __nv_bfloat16* __restrict__ blo,
    int k0, int tid) {
    {   // A: 2 mats x 32 rows x 8
        int mat = tid >> 8, v = tid & 255;
        int row = v >> 3, c = v & 7;
        const __nv_bfloat16* base = mat ? alo : ahi;
        const void* src = base + (long)row * HH + k0 + (c << 3);
        uint32_t dst = sbuf + mat * 4608 + row * 144 + (c << 4);
        asm volatile("cp.async.cg.shared.global [%0], [%1], 16;" :: "r"(dst), "l"(src));
    }
#pragma unroll
    for (int i = 0; i < 2; ++i) {   // B: 2 mats x 64 rows x 8
        int u = tid + (i << 9);
        int mat = u >> 9, v = u & 511;
        int row = v >> 3, c = v & 7;
        const __nv_bfloat16* base = mat ? blo : bhi;
        const void* src = base + (long)row * HH + k0 + (c << 3);
        uint32_t dst = sbuf + 9216 + mat * MATSZ + row * 144 + (c << 4);
        asm volatile("cp.async.cg.shared.global [%0], [%1], 16;" :: "r"(dst), "l"(src));
    }
}
static __device__ __forceinline__ void issue_chunk2(
    uint32_t sbuf,
    const __nv_bfloat16* __restrict__ ahi, const __nv_bfloat16* __restrict__ alo,
    const __nv_bfloat16* __restrict__ bhi, const __nv_bfloat16* __restrict__ blo,
    int k0, int tid) {
    issue_sub2(sbuf, ahi, alo, bhi, blo, k0, tid);
    issue_sub2(sbuf + P2SUB, ahi, alo, bhi, blo, k0 + 64, tid);
    asm volatile("cp.async.commit_group;" ::: "memory");
}

// ---------------- phase1 compute: warp tile 32x32, one kstep ----------------
static __device__ __forceinline__ void compute_p1(
    const char* buf, int grp, int wm, int wn,
    FragC& c00, FragC& c01, FragC& c10, FragC& c11) {
    const __nv_bfloat16* Ah = reinterpret_cast<const __nv_bfloat16*>(buf);
    const __nv_bfloat16* Al = reinterpret_cast<const __nv_bfloat16*>(buf + MATSZ);
    const __nv_bfloat16* Bh = reinterpret_cast<const __nv_bfloat16*>(buf + 2 * MATSZ);
    const __nv_bfloat16* Bl = reinterpret_cast<const __nv_bfloat16*>(buf + 3 * MATSZ);
    const int ko = grp << 4;
    FragA ah0, ah1, al0, al1;
    FragB bh0, bh1, bl0, bl1;
    wmma::load_matrix_sync(ah0, Ah + (wm * 32) * LDMAB + ko, LDMAB);
    wmma::load_matrix_sync(ah1, Ah + (wm * 32 + 16) * LDMAB + ko, LDMAB);
    wmma::load_matrix_sync(bh0, Bh + (wn * 32) * LDMAB + ko, LDMAB);
    wmma::load_matrix_sync(bh1, Bh + (wn * 32 + 16) * LDMAB + ko, LDMAB);
    wmma::mma_sync(c00, ah0, bh0, c00);
    wmma::mma_sync(c01, ah0, bh1, c01);
    wmma::mma_sync(c10, ah1, bh0, c10);
    wmma::mma_sync(c11, ah1, bh1, c11);
    wmma::load_matrix_sync(bl0, Bl + (wn * 32) * LDMAB + ko, LDMAB);
    wmma::load_matrix_sync(bl1, Bl + (wn * 32 + 16) * LDMAB + ko, LDMAB);
    wmma::mma_sync(c00, ah0, bl0, c00);
    wmma::mma_sync(c01, ah0, bl1, c01);
    wmma::mma_sync(c10, ah1, bl0, c10);
    wmma::mma_sync(c11, ah1, bl1, c11);
    wmma::load_matrix_sync(al0, Al + (wm * 32) * LDMAB + ko, LDMAB);
    wmma::load_matrix_sync(al1, Al + (wm * 32 + 16) * LDMAB + ko, LDMAB);
    wmma::mma_sync(c00, al0, bh0, c00);
    wmma::mma_sync(c01, al0, bh1, c01);
    wmma::mma_sync(c10, al1, bh0, c10);
    wmma::mma_sync(c11, al1, bh1, c11);
}

// ---------------- phase2 compute: warp tile 16x32, one kstep ----------------
static __device__ __forceinline__ void compute_p2(
    const char* buf, int grp, int wm, int wn, FragC& c0, FragC& c1) {
    const __nv_bfloat16* Ah = reinterpret_cast<const __nv_bfloat16*>(buf);
    const __nv_bfloat16* Al = reinterpret_cast<const __nv_bfloat16*>(buf + 4608);
    const __nv_bfloat16* Bh = reinterpret_cast<const __nv_bfloat16*>(buf + 9216);
    const __nv_bfloat16* Bl = reinterpret_cast<const __nv_bfloat16*>(buf + 9216 + MATSZ);
    const int ko = grp << 4;
    FragA ah, al;
    FragB bh0, bh1, bl0, bl1;
    wmma::load_matrix_sync(ah, Ah + (wm * 16) * LDMAB + ko, LDMAB);
    wmma::load_matrix_sync(bh0, Bh + (wn * 32) * LDMAB + ko, LDMAB);
    wmma::load_matrix_sync(bh1, Bh + (wn * 32 + 16) * LDMAB + ko, LDMAB);
    wmma::mma_sync(c0, ah, bh0, c0);
    wmma::mma_sync(c1, ah, bh1, c1);
    wmma::load_matrix_sync(bl0, Bl + (wn * 32) * LDMAB + ko, LDMAB);
    wmma::load_matrix_sync(bl1, Bl + (wn * 32 + 16) * LDMAB + ko, LDMAB);
    wmma::mma_sync(c0, ah, bl0, c0);
    wmma::mma_sync(c1, ah, bl1, c1);
    wmma::load_matrix_sync(al, Al + (wm * 16) * LDMAB + ko, LDMAB);
    wmma::mma_sync(c0, al, bh0, c0);
    wmma::mma_sync(c1, al, bh1, c1);
}

// ---------------- phase1 GEMM: 64x64x1024, K=128 chunks, 2-stage ----------
static __device__ void run_gemm1(
    char* sm, uint32_t sbase,
    const __nv_bfloat16* __restrict__ ahi, const __nv_bfloat16* __restrict__ alo,
    const __nv_bfloat16* __restrict__ bhi, const __nv_bfloat16* __restrict__ blo,
    int tid, int grp, int wm, int wn) {
    FragC c00, c01, c10, c11;
    wmma::fill_fragment(c00, 0.f);
    wmma::fill_fragment(c01, 0.f);
    wmma::fill_fragment(c10, 0.f);
    wmma::fill_fragment(c11, 0.f);

    issue_chunk1(sbase + 1024, ahi, alo, bhi, blo, 0, tid);

#pragma unroll 1
    for (int c = 0; c < 8; ++c) {
        asm volatile("cp.async.wait_group 0;" ::: "memory");
        __syncthreads();
        if (c < 7)
            issue_chunk1(sbase + 1024 + ((c + 1) & 1) * P1CH,
                         ahi, alo, bhi, blo, (c + 1) * 128, tid);
        const char* buf = sm + 1024 + (c & 1) * P1CH;
        compute_p1(buf, grp, wm, wn, c00, c01, c10, c11);
        compute_p1(buf + P1SUB, grp, wm, wn, c00, c01, c10, c11);
    }
    float* sCg = reinterpret_cast<float*>(sm + CBASE) + grp * (64 * LDMC);
    wmma::store_matrix_sync(sCg + (wm * 32) * LDMC + wn * 32, c00, LDMC, wmma::mem_row_major);
    wmma::store_matrix_sync(sCg + (wm * 32) * LDMC + wn * 32 + 16, c01, LDMC, wmma::mem_row_major);
    wmma::store_matrix_sync(sCg + (wm * 32 + 16) * LDMC + wn * 32, c10, LDMC, wmma::mem_row_major);
    wmma::store_matrix_sync(sCg + (wm * 32 + 16) * LDMC + wn * 32 + 16, c11, LDMC, wmma::mem_row_major);
    __syncthreads();
}

// ---------------- phase2 GEMM: 32x64x1024, K=128 chunks, 2-stage ----------
static __device__ void run_gemm2(
    char* sm, uint32_t sbase,
    const __nv_bfloat16* __restrict__ ahi, const __nv_bfloat16* __restrict__ alo,
    const __nv_bfloat16* __restrict__ bhi, const __nv_bfloat16* __restrict__ blo,
    int tid, int grp, int wm, int wn) {
    FragC c0, c1;
    wmma::fill_fragment(c0, 0.f);
    wmma::fill_fragment(c1, 0.f);

    issue_chunk2(sbase + 1024, ahi, alo, bhi, blo, 0, tid);

#pragma unroll 1
    for (int c = 0; c < 8; ++c) {
        asm volatile("cp.async.wait_group 0;" ::: "memory");
        __syncthreads();
        if (c < 7)
            issue_chunk2(sbase + 1024 + ((c + 1) & 1) * P2CH,
                         ahi, alo, bhi, blo, (c + 1) * 128, tid);
        const char* buf = sm + 1024 + (c & 1) * P2CH;
        compute_p2(buf, grp, wm, wn, c0, c1);
        compute_p2(buf + P2SUB, grp, wm, wn, c0, c1);
    }
    float* sCg = reinterpret_cast<float*>(sm + CBASE) + grp * (32 * LDMC);
    wmma::store_matrix_sync(sCg + (wm * 16) * LDMC + wn * 32, c0, LDMC, wmma::mem_row_major);
    wmma::store_matrix_sync(sCg + (wm * 16) * LDMC + wn * 32 + 16, c1, LDMC, wmma::mem_row_major);
    __syncthreads();
}

// ---------------- main persistent kernel ----------------
__global__ void __launch_bounds__(NTHR, 1)
gru_tc(const int* __restrict__ x,
       const float* __restrict__ Wph,
       const float* __restrict__ bp,
       float* __restrict__ out) {
    extern __shared__ __align__(16) char smem[];
    const uint32_t sbase = smem_u32(smem);
    const int tid = threadIdx.x;
    const int wid = tid >> 5;
    const int lane = tid & 31;
    const int cta = blockIdx.x;
    const int grp = wid >> 2;            // K group 0..3
    const int wpos = wid & 3;
    const int wm = wpos & 1, wn = wpos >> 1;

    for (int i = cta * NTHR + tid; i < BB * HH; i += NCTA * NTHR) {
        g_h[i] = 0.f;
        g_ha[0][i] = __float2bfloat16(0.f);
        g_ha[1][i] = __float2bfloat16(0.f);
    }
    grid_sync();

    // phase1: 128 tiles = 4 M-strips(64) x (16 z + 16 r) N-tiles(64)
    const int p1_bm = (cta & 3) << 6;
    const int p1_nt = cta >> 2;
    const int p1_gate = p1_nt >> 4;
    const int p1_jb = (p1_nt & 15) << 6;
    // phase2: 128 tiles = 8 M-strips(32) x 16 N-tiles(64)
    const int p2_bm = (cta & 7) << 5;
    const int p2_jb = (cta >> 3) << 6;

    const float* sC = reinterpret_cast<const float*>(smem + CBASE);

    for (int t = 0; t < TT; ++t) {
        // ============ phase 1: z / r gates ============
        run_gemm1(smem, sbase,
                  &g_ha[0][p1_bm * HH], &g_ha[1][p1_bm * HH],
                  &g_w[p1_gate][0][p1_jb * HH], &g_w[p1_gate][1][p1_jb * HH],
                  tid, grp, wm, wn);
        {
            const int er = tid >> 3;              // 0..63
            const int ecb = (tid & 7) << 3;       // 8 cols
            const float* cr = sC + er * LDMC + ecb;
            float v[8];
            {
                float4 a0 = *reinterpret_cast<const float4*>(cr);
                float4 a1 = *reinterpret_cast<const float4*>(cr + 4);
#pragma unroll
                for (int g = 1; g < 4; ++g) {
                    const float* crg = cr + g * (64 * LDMC);
                    float4 b0 = *reinterpret_cast<const float4*>(crg);
                    float4 b1 = *reinterpret_cast<const float4*>(crg + 4);
                    a0.x += b0.x; a0.y += b0.y; a0.z += b0.z; a0.w += b0.w;
                    a1.x += b1.x; a1.y += b1.y; a1.z += b1.z; a1.w += b1.w;
                }
                v[0] = a0.x; v[1] = a0.y; v[2] = a0.z; v[3] = a0.w;
                v[4] = a1.x; v[5] = a1.y; v[6] = a1.z; v[7] = a1.w;
            }
            const int b = p1_bm + er;
            const int tok = x[b * TT + t];
            const float* __restrict__ pre = &g_pre[p1_gate][tok][p1_jb + ecb];
            if (p1_gate == 0) {
                float* __restrict__ dst = &g_z[b * HH + p1_jb + ecb];
#pragma unroll
                for (int q = 0; q < 2; ++q) {
                    float4 p = *reinterpret_cast<const float4*>(pre + q * 4);
                    float4 o;
                    o.x = sigf(v[q * 4 + 0] + p.x);
                    o.y = sigf(v[q * 4 + 1] + p.y);
                    o.z = sigf(v[q * 4 + 2] + p.z);
                    o.w = sigf(v[q * 4 + 3] + p.w);
                    *reinterpret_cast<float4*>(dst + q * 4) = o;
                }
            } else {
                const float* __restrict__ hrow = &g_h[b * HH + p1_jb + ecb];
                float hr[8];
#pragma unroll
                for (int q = 0; q < 2; ++q) {
                    float4 p = *reinterpret_cast<const float4*>(pre + q * 4);
                    float4 h4 = *reinterpret_cast<const float4*>(hrow + q * 4);
                    hr[q * 4 + 0] = sigf(v[q * 4 + 0] + p.x) * h4.x;
                    hr[q * 4 + 1] = sigf(v[q * 4 + 1] + p.y) * h4.y;
                    hr[q * 4 + 2] = sigf(v[q * 4 + 2] + p.z) * h4.z;
                    hr[q * 4 + 3] = sigf(v[q * 4 + 3] + p.w) * h4.w;
                }
                uint32_t phi[4], plo[4];
#pragma unroll
                for (int q = 0; q < 4; ++q) {
                    float a = hr[2 * q], bx = hr[2 * q + 1];
                    float ea = a - __bfloat162float(__float2bfloat16(a));
                    float eb = bx - __bfloat162float(__float2bfloat16(bx));
                    phi[q] = pack_bf2(a, bx);
                    plo[q] = pack_bf2(ea, eb);
                }
                *reinterpret_cast<uint4*>(&g_hra[0][b * HH + p1_jb + ecb]) =
                    make_uint4(phi[0], phi[1], phi[2], phi[3]);
                *reinterpret_cast<uint4*>(&g_hra[1][b * HH + p1_jb + ecb]) =
                    make_uint4(plo[0], plo[1], plo[2], plo[3]);
            }
        }
        grid_sync();

        // ============ phase 2: candidate + state update ============
        run_gemm2(smem, sbase,
                  &g_hra[0][p2_bm * HH], &g_hra[1][p2_bm * HH],
                  &g_w[2][0][p2_jb * HH], &g_w[2][1][p2_jb * HH],
                  tid, grp, wm, wn);
        {
            const int er = tid >> 4;              // 0..31
            const int ecb = (tid & 15) << 2;      // 4 cols
            const float* cr = sC + er * LDMC + ecb;
            float4 v = *reinterpret_cast<const float4*>(cr);
#pragma unroll
            for (int g = 1; g < 4; ++g) {
                float4 bq = *reinterpret_cast<const float4*>(cr + g * (32 * LDMC));
                v.x += bq.x; v.y += bq.y; v.z += bq.z; v.w += bq.w;
            }
            const int b = p2_bm + er;
            const int tok = x[b * TT + t];
            const float* __restrict__ pre = &g_pre[2][tok][p2_jb + ecb];
            float* __restrict__ hrow = &g_h[b * HH + p2_jb + ecb];
            const float* __restrict__ zrow = &g_z[b * HH + p2_jb + ecb];
            float4 p = *reinterpret_cast<const float4*>(pre);
            float4 h4 = *reinterpret_cast<const float4*>(hrow);
            float4 z4 = *reinterpret_cast<const float4*>(zrow);
            float hn[4];
            hn[0] = h4.x + z4.x * (fast_tanh(v.x + p.x) - h4.x);
            hn[1] = h4.y + z4.y * (fast_tanh(v.y + p.y) - h4.y);
            hn[2] = h4.z + z4.z * (fast_tanh(v.z + p.z) - h4.z);
            hn[3] = h4.w + z4.w * (fast_tanh(v.w + p.w) - h4.w);
            *reinterpret_cast<float4*>(hrow) = make_float4(hn[0], hn[1], hn[2], hn[3]);
            uint32_t phi[2], plo[2];
#pragma unroll
            for (int q = 0; q < 2; ++q) {
                float a = hn[2 * q], bx = hn[2 * q + 1];
                float ea = a - __bfloat162float(__float2bfloat16(a));
                float eb = bx - __bfloat162float(__float2bfloat16(bx));
                phi[q] = pack_bf2(a, bx);
                plo[q] = pack_bf2(ea, eb);
            }
            *reinterpret_cast<uint2*>(&g_ha[0][b * HH + p2_jb + ecb]) = make_uint2(phi[0], phi[1]);
            *reinterpret_cast<uint2*>(&g_ha[1][b * HH + p2_jb + ecb]) = make_uint2(plo[0], plo[1]);
        }
        grid_sync();
    }

    // ============ output projection ============
    const int warpId = (cta << 4) + wid;
    const int nWarps = NCTA << 4;
    for (int oc = warpId; oc < BB * CC; oc += nWarps) {
        const int b = oc / CC;
        const int c = oc - b * CC;
        const float* hrow = &g_h[b * HH];
        const float* wrow = &Wph[c * HH];
        float s = 0.f;
        for (int j = lane; j < HH; j += 32)
            s += hrow[j] * wrow[j];
#pragma unroll
        for (int off = 16; off; off >>= 1)
            s += __shfl_xor_sync(0xffffffffu, s, off);
        if (lane == 0) out[oc] = s + bp[c];
    }
}

// ---------------- launch ----------------
extern "C" void kernel_launch(void* const* d_in, const int* in_sizes, int n_in,
                              void* d_out, int out_size) {
    const int*   x     = (const int*)d_in[0];
    const float* embed = (const float*)d_in[1];
    const float* Wz    = (const float*)d_in[2];
    const float* Wr    = (const float*)d_in[3];
    const float* Wc    = (const float*)d_in[4];
    const float* Wph   = (const float*)d_in[5];
    const float* bp    = (const float*)d_in[6];
    float* out = (float*)d_out;

    cudaFuncSetAttribute(gru_tc, cudaFuncAttributeMaxDynamicSharedMemorySize, SMEM_TOTAL);

    const long total = 3L * HH * HH + 3L * VV * HH;
    precompute_kernel<<<(unsigned)((total + 255) / 256), 256>>>(embed, Wz, Wr, Wc);
    gru_tc<<<NCTA, NTHR, SMEM_TOTAL>>>(x, Wph, bp, out);
}

// round 10
// speedup vs baseline: 3.3690x; 1.1155x over previous
#include <cuda_runtime.h>
#include <cuda_bf16.h>
#include <mma.h>
#include <cstdint>
#include <math.h>

using namespace nvcuda;

#define BB 256
#define TT 512
#define VV 10
#define EE 10
#define HH 1024
#define CC 10
#define KW 1034
#define NCTA 128
#define NTHR 512

// ---------------- device scratch ----------------
__device__ float g_h[BB * HH];
__device__ float g_z[BB * HH];
__device__ __nv_bfloat16 g_ha[2][BB * HH];    // h hi/lo   (phase1 A)
__device__ __nv_bfloat16 g_hra[2][BB * HH];   // h*r hi/lo (phase2 A)
__device__ __nv_bfloat16 g_w[3][2][HH * HH];  // weight splits, K-major [j*HH+k]
__device__ float g_pre[3][VV][HH];            // x-path tables
__device__ unsigned g_count;
__device__ volatile unsigned g_phase;

// smem: [0,1024) pad; 3 stages of K=128 chunks at 1024 + s*P1CH.
// C partials ALIAS stage 0 (written only after mainloop, read in epilogue).
// phase1 K=64 sub-block: Ahi 64x144B | Alo | Bhi | Blo (36864B); chunk = 2 subs
// phase2 K=64 sub-block: Ahi 32x144B | Alo | Bhi 64x144B | Blo (27648B); chunk = 2
#define P1SUB  36864
#define P1CH   73728
#define P2SUB  27648
#define P2CH   55296
#define MATSZ  9216
#define LDMAB  72
#define LDMC   68
#define CBASE  1024
#define SMEM_TOTAL (1024 + 3 * P1CH)

typedef wmma::fragment<wmma::accumulator, 16, 16, 16, float> FragC;
typedef wmma::fragment<wmma::matrix_a, 16, 16, 16, __nv_bfloat16, wmma::row_major> FragA;
typedef wmma::fragment<wmma::matrix_b, 16, 16, 16, __nv_bfloat16, wmma::col_major> FragB;

// ---------------- math ----------------
static __device__ __forceinline__ float sigf(float v) {
    return __fdividef(1.f, 1.f + __expf(-v));
}
static __device__ __forceinline__ float fast_tanh(float v) {
    v = fminf(fmaxf(v, -15.f), 15.f);
    float e = __expf(-2.f * v);
    return __fdividef(1.f - e, 1.f + e);
}
static __device__ __forceinline__ uint32_t pack_bf2(float a, float b) {
    __nv_bfloat16 x = __float2bfloat16(a), y = __float2bfloat16(b);
    return ((uint32_t)__bfloat16_as_ushort(y) << 16) | (uint32_t)__bfloat16_as_ushort(x);
}
static __device__ __forceinline__ uint32_t smem_u32(const void* p) {
    uint32_t a;
    asm("{ .reg .u64 t; cvta.to.shared.u64 t, %1; cvt.u32.u64 %0, t; }" : "=r"(a) : "l"(p));
    return a;
}
#define CP16(dst, src) \
    asm volatile("cp.async.cg.shared.global [%0], [%1], 16;" :: "r"(dst), "l"(src))
#define CPCOMMIT() asm volatile("cp.async.commit_group;" ::: "memory")

// ---------------- grid barrier ----------------
static __device__ __forceinline__ void grid_sync() {
    __syncthreads();
    if (threadIdx.x == 0) {
        __threadfence();
        unsigned ph = g_phase;
        if (atomicAdd(&g_count, 1u) == gridDim.x - 1u) {
            g_count = 0u;
            __threadfence();
            g_phase = ph + 1u;
        } else {
            while (g_phase == ph) { __nanosleep(32); }
        }
        __threadfence();
    }
    __syncthreads();
}

// ---------------- precompute ----------------
__global__ void precompute_kernel(const float* __restrict__ embed,
                                  const float* __restrict__ Wz,
                                  const float* __restrict__ Wr,
                                  const float* __restrict__ Wc) {
    long idx = (long)blockIdx.x * 256 + threadIdx.x;
    const long NSPLIT = 3L * HH * HH;
    if (idx < NSPLIT) {
        int g = (int)(idx / (HH * HH));
        int rem = (int)(idx % (HH * HH));
        int j = rem / HH, k = rem % HH;
        const float* Wg = (g == 0) ? Wz : (g == 1) ? Wr : Wc;
        float w = Wg[(long)j * KW + k];
        __nv_bfloat16 hi = __float2bfloat16(w);
        g_w[g][0][rem] = hi;
        g_w[g][1][rem] = __float2bfloat16(w - __bfloat162float(hi));
    } else {
        long r = idx - NSPLIT;
        if (r < 3L * VV * HH) {
            int g = (int)(r / (VV * HH));
            int rem = (int)(r % (VV * HH));
            int v = rem / HH, j = rem % HH;
            const float* Wg = (g == 0) ? Wz : (g == 1) ? Wr : Wc;
            float s = 0.f;
#pragma unroll
            for (int e = 0; e < EE; ++e)
                s += embed[v * EE + e] * Wg[(long)j * KW + HH + e];
            g_pre[g][v][j] = s;
        }
    }
}

// ---------------- cp.async staging pieces ----------------
// phase1 sub-block A: 2 mats x 64 rows (2 ops/thread)
static __device__ __forceinline__ void sub1_A(
    uint32_t sbuf, const __nv_bfloat16* __restrict__ ahi,
    const __nv_bfloat16* __restrict__ alo, int k0, int tid) {
#pragma unroll
    for (int i = 0; i < 2; ++i) {
        const __nv_bfloat16* base = i ? alo : ahi;
        int row = tid >> 3, c = tid & 7;
        CP16(sbuf + i * MATSZ + row * 144 + (c << 4),
             base + (long)row * HH + k0 + (c << 3));
    }
}
// phase1 sub-block B: 2 mats x 64 rows (2 ops/thread)
static __device__ __forceinline__ void sub1_B(
    uint32_t sbuf, const __nv_bfloat16* __restrict__ bhi,
    const __nv_bfloat16* __restrict__ blo, int k0, int tid) {
#pragma unroll
    for (int i = 0; i < 2; ++i) {
        const __nv_bfloat16* base = i ? blo : bhi;
        int row = tid >> 3, c = tid & 7;
        CP16(sbuf + (2 + i) * MATSZ + row * 144 + (c << 4),
             base + (long)row * HH + k0 + (c << 3));
    }
}
static __device__ __forceinline__ void chunk1_A(
    uint32_t sbuf, const __nv_bfloat16* ahi, const __nv_bfloat16* alo, int k0, int tid) {
    sub1_A(sbuf, ahi, alo, k0, tid);
    sub1_A(sbuf + P1SUB, ahi, alo, k0 + 64, tid);
}
static __device__ __forceinline__ void chunk1_B(
    uint32_t sbuf, const __nv_bfloat16* bhi, const __nv_bfloat16* blo, int k0, int tid) {
    sub1_B(sbuf, bhi, blo, k0, tid);
    sub1_B(sbuf + P1SUB, bhi, blo, k0 + 64, tid);
}

// phase2 sub-block A: 2 mats x 32 rows (1 op/thread)
static __device__ __forceinline__ void sub2_A(
    uint32_t sbuf, const __nv_bfloat16* __restrict__ ahi,
    const __nv_bfloat16* __restrict__ alo, int k0, int tid) {
    int mat = tid >> 8, v = tid & 255;
    int row = v >> 3, c = v & 7;
    const __nv_bfloat16* base = mat ? alo : ahi;
    CP16(sbuf + mat * 4608 + row * 144 + (c << 4),
         base + (long)row * HH + k0 + (c << 3));
}
// phase2 sub-block B: 2 mats x 64 rows (2 ops/thread)
static __device__ __forceinline__ void sub2_B(
    uint32_t sbuf, const __nv_bfloat16* __restrict__ bhi,
    const __nv_bfloat16* __restrict__ blo, int k0, int tid) {
#pragma unroll
    for (int i = 0; i < 2; ++i) {
        int u = tid + (i << 9);
        int mat = u >> 9, v = u & 511;
        int row = v >> 3, c = v & 7;
        const __nv_bfloat16* base = mat ? blo : bhi;
        CP16(sbuf + 9216 + mat * MATSZ + row * 144 + (c << 4),
             base + (long)row * HH + k0 + (c << 3));
    }
}
static __device__ __forceinline__ void chunk2_A(
    uint32_t sbuf, const __nv_bfloat16* ahi, const __nv_bfloat16* alo, int k0, int tid) {
    sub2_A(sbuf, ahi, alo, k0, tid);
    sub2_A(sbuf + P2SUB, ahi, alo, k0 + 64, tid);
}
static __device__ __forceinline__ void chunk2_B(
    uint32_t sbuf, const __nv_bfloat16* bhi, const __nv_bfloat16* blo, int k0, int tid) {
    sub2_B(sbuf, bhi, blo, k0, tid);
    sub2_B(sbuf + P2SUB, bhi, blo, k0 + 64, tid);
}

// pre-barrier B prefetch (chunks 0..2, ONE commit group)
static __device__ __forceinline__ void preB1(
    uint32_t sbase, const __nv_bfloat16* bhi, const __nv_bfloat16* blo, int tid) {
#pragma unroll
    for (int ch = 0; ch < 3; ++ch)
        chunk1_B(sbase + 1024 + ch * P1CH, bhi, blo, ch * 128, tid);
    CPCOMMIT();
}
static __device__ __forceinline__ void preB2(
    uint32_t sbase, const __nv_bfloat16* bhi, const __nv_bfloat16* blo, int tid) {
#pragma unroll
    for (int ch = 0; ch < 3; ++ch)
        chunk2_B(sbase + 1024 + ch * P2CH, bhi, blo, ch * 128, tid);
    CPCOMMIT();
}

// ---------------- phase1 compute: warp tile 32x32, one kstep ----------------
static __device__ __forceinline__ void compute_p1(
    const char* buf, int grp, int wm, int wn,
    FragC& c00, FragC& c01, FragC& c10, FragC& c11) {
    const __nv_bfloat16* Ah = reinterpret_cast<const __nv_bfloat16*>(buf);
    const __nv_bfloat16* Al = reinterpret_cast<const __nv_bfloat16*>(buf + MATSZ);
    const __nv_bfloat16* Bh = reinterpret_cast<const __nv_bfloat16*>(buf + 2 * MATSZ);
    const __nv_bfloat16* Bl = reinterpret_cast<const __nv_bfloat16*>(buf + 3 * MATSZ);
    const int ko = grp << 4;
    FragA ah0, ah1, al0, al1;
    FragB bh0, bh1, bl0, bl1;
    wmma::load_matrix_sync(ah0, Ah + (wm * 32) * LDMAB + ko, LDMAB);
    wmma::load_matrix_sync(ah1, Ah + (wm * 32 + 16) * LDMAB + ko, LDMAB);
    wmma::load_matrix_sync(bh0, Bh + (wn * 32) * LDMAB + ko, LDMAB);
    wmma::load_matrix_sync(bh1, Bh + (wn * 32 + 16) * LDMAB + ko, LDMAB);
    wmma::mma_sync(c00, ah0, bh0, c00);
    wmma::mma_sync(c01, ah0, bh1, c01);
    wmma::mma_sync(c10, ah1, bh0, c10);
    wmma::mma_sync(c11, ah1, bh1, c11);
    wmma::load_matrix_sync(bl0, Bl + (wn * 32) * LDMAB + ko, LDMAB);
    wmma::load_matrix_sync(bl1, Bl + (wn * 32 + 16) * LDMAB + ko, LDMAB);
    wmma::mma_sync(c00, ah0, bl0, c00);
    wmma::mma_sync(c01, ah0, bl1, c01);
    wmma::mma_sync(c10, ah1, bl0, c10);
    wmma::mma_sync(c11, ah1, bl1, c11);
    wmma::load_matrix_sync(al0, Al + (wm * 32) * LDMAB + ko, LDMAB);
    wmma::load_matrix_sync(al1, Al + (wm * 32 + 16) * LDMAB + ko, LDMAB);
    wmma::mma_sync(c00, al0, bh0, c00);
    wmma::mma_sync(c01, al0, bh1, c01);
    wmma::mma_sync(c10, al1, bh0, c10);
    wmma::mma_sync(c11, al1, bh1, c11);
}

// ---------------- phase2 compute: warp tile 16x32, one kstep ----------------
static __device__ __forceinline__ void compute_p2(
    const char* buf, int grp, int wm, int wn, FragC& c0, FragC& c1) {
    const __nv_bfloat16* Ah = reinterpret_cast<const __nv_bfloat16*>(buf);
    const __nv_bfloat16* Al = reinterpret_cast<const __nv_bfloat16*>(buf + 4608);
    const __nv_bfloat16* Bh = reinterpret_cast<const __nv_bfloat16*>(buf + 9216);
    const __nv_bfloat16* Bl = reinterpret_cast<const __nv_bfloat16*>(buf + 9216 + MATSZ);
    const int ko = grp << 4;
    FragA ah, al;
    FragB bh0, bh1, bl0, bl1;
    wmma::load_matrix_sync(ah, Ah + (wm * 16) * LDMAB + ko, LDMAB);
    wmma::load_matrix_sync(bh0, Bh + (wn * 32) * LDMAB + ko, LDMAB);
    wmma::load_matrix_sync(bh1, Bh + (wn * 32 + 16) * LDMAB + ko, LDMAB);
    wmma::mma_sync(c0, ah, bh0, c0);
    wmma::mma_sync(c1, ah, bh1, c1);
    wmma::load_matrix_sync(bl0, Bl + (wn * 32) * LDMAB + ko, LDMAB);
    wmma::load_matrix_sync(bl1, Bl + (wn * 32 + 16) * LDMAB + ko, LDMAB);
    wmma::mma_sync(c0, ah, bl0, c0);
    wmma::mma_sync(c1, ah, bl1, c1);
    wmma::load_matrix_sync(al, Al + (wm * 16) * LDMAB + ko, LDMAB);
    wmma::mma_sync(c0, al, bh0, c0);
    wmma::mma_sync(c1, al, bh1, c1);
}

// ---------------- phase1 GEMM: 64x64x1024, 3-stage, B pre-staged ----------
static __device__ void run_gemm1(
    char* sm, uint32_t sbase,
    const __nv_bfloat16* __restrict__ ahi, const __nv_bfloat16* __restrict__ alo,
    const __nv_bfloat16* __restrict__ bhi, const __nv_bfloat16* __restrict__ blo,
    int tid, int grp, int wm, int wn) {
    FragC c00, c01, c10, c11;
    wmma::fill_fragment(c00, 0.f);
    wmma::fill_fragment(c01, 0.f);
    wmma::fill_fragment(c10, 0.f);
    wmma::fill_fragment(c11, 0.f);

    chunk1_A(sbase + 1024, ahi, alo, 0, tid);            CPCOMMIT();
    chunk1_A(sbase + 1024 + P1CH, ahi, alo, 128, tid);   CPCOMMIT();

#pragma unroll 1
    for (int c = 0; c < 8; ++c) {
        if (c + 2 <= 7) {
            uint32_t sb = sbase + 1024 + ((c + 2) % 3) * P1CH;
            chunk1_A(sb, ahi, alo, (c + 2) * 128, tid);
            if (c + 2 >= 3) chunk1_B(sb, bhi, blo, (c + 2) * 128, tid);
            CPCOMMIT();
        }
        int wrem = 7 - c;
        if (wrem >= 2)      asm volatile("cp.async.wait_group 2;" ::: "memory");
        else if (wrem == 1) asm volatile("cp.async.wait_group 1;" ::: "memory");
        else                asm volatile("cp.async.wait_group 0;" ::: "memory");
        __syncthreads();
        const char* buf = sm + 1024 + (c % 3) * P1CH;
        compute_p1(buf, grp, wm, wn, c00, c01, c10, c11);
        compute_p1(buf + P1SUB, grp, wm, wn, c00, c01, c10, c11);
    }
    // C partials alias stage0: last reader of stage0 was chunk 6 (synced at iter 7)
    float* sCg = reinterpret_cast<float*>(sm + CBASE) + grp * (64 * LDMC);
    wmma::store_matrix_sync(sCg + (wm * 32) * LDMC + wn * 32, c00, LDMC, wmma::mem_row_major);
    wmma::store_matrix_sync(sCg + (wm * 32) * LDMC + wn * 32 + 16, c01, LDMC, wmma::mem_row_major);
    wmma::store_matrix_sync(sCg + (wm * 32 + 16) * LDMC + wn * 32, c10, LDMC, wmma::mem_row_major);
    wmma::store_matrix_sync(sCg + (wm * 32 + 16) * LDMC + wn * 32 + 16, c11, LDMC, wmma::mem_row_major);
    __syncthreads();
}

// ---------------- phase2 GEMM: 32x64x1024, 3-stage, B pre-staged ----------
static __device__ void run_gemm2(
    char* sm, uint32_t sbase,
    const __nv_bfloat16* __restrict__ ahi, const __nv_bfloat16* __restrict__ alo,
    const __nv_bfloat16* __restrict__ bhi, const __nv_bfloat16* __restrict__ blo,
    int tid, int grp, int wm, int wn) {
    FragC c0, c1;
    wmma::fill_fragment(c0, 0.f);
    wmma::fill_fragment(c1, 0.f);

    chunk2_A(sbase + 1024, ahi, alo, 0, tid);            CPCOMMIT();
    chunk2_A(sbase + 1024 + P2CH, ahi, alo, 128, tid);   CPCOMMIT();

#pragma unroll 1
    for (int c = 0; c < 8; ++c) {
        if (c + 2 <= 7) {
            uint32_t sb = sbase + 1024 + ((c + 2) % 3) * P2CH;
            chunk2_A(sb, ahi, alo, (c + 2) * 128, tid);
            if (c + 2 >= 3) chunk2_B(sb, bhi, blo, (c + 2) * 128, tid);
            CPCOMMIT();
        }
        int wrem = 7 - c;
        if (wrem >= 2)      asm volatile("cp.async.wait_group 2;" ::: "memory");
        else if (wrem == 1) asm volatile("cp.async.wait_group 1;" ::: "memory");
        else                asm volatile("cp.async.wait_group 0;" ::: "memory");
        __syncthreads();
        const char* buf = sm + 1024 + (c % 3) * P2CH;
        compute_p2(buf, grp, wm, wn, c0, c1);
        compute_p2(buf + P2SUB, grp, wm, wn, c0, c1);
    }
    float* sCg = reinterpret_cast<float*>(sm + CBASE) + grp * (32 * LDMC);
    wmma::store_matrix_sync(sCg + (wm * 16) * LDMC + wn * 32, c0, LDMC, wmma::mem_row_major);
    wmma::store_matrix_sync(sCg + (wm * 16) * LDMC + wn * 32 + 16, c1, LDMC, wmma::mem_row_major);
    __syncthreads();
}

// ---------------- main persistent kernel ----------------
__global__ void __launch_bounds__(NTHR, 1)
gru_tc(const int* __restrict__ x,
       const float* __restrict__ Wph,
       const float* __restrict__ bp,
       float* __restrict__ out) {
    extern __shared__ __align__(16) char smem[];
    const uint32_t sbase = smem_u32(smem);
    const int tid = threadIdx.x;
    const int wid = tid >> 5;
    const int lane = tid & 31;
    const int cta = blockIdx.x;
    const int grp = wid >> 2;            // K group 0..3
    const int wpos = wid & 3;
    const int wm = wpos & 1, wn = wpos >> 1;

    for (int i = cta * NTHR + tid; i < BB * HH; i += NCTA * NTHR) {
        g_h[i] = 0.f;
        g_ha[0][i] = __float2bfloat16(0.f);
        g_ha[1][i] = __float2bfloat16(0.f);
    }

    // phase1: 128 tiles = 4 M-strips(64) x (16 z + 16 r) N-tiles(64)
    const int p1_bm = (cta & 3) << 6;
    const int p1_nt = cta >> 2;
    const int p1_gate = p1_nt >> 4;
    const int p1_jb = (p1_nt & 15) << 6;
    // phase2: 128 tiles = 8 M-strips(32) x 16 N-tiles(64)
    const int p2_bm = (cta & 7) << 5;
    const int p2_jb = (cta >> 3) << 6;

    const __nv_bfloat16* w1hi = &g_w[p1_gate][0][p1_jb * HH];
    const __nv_bfloat16* w1lo = &g_w[p1_gate][1][p1_jb * HH];
    const __nv_bfloat16* w2hi = &g_w[2][0][p2_jb * HH];
    const __nv_bfloat16* w2lo = &g_w[2][1][p2_jb * HH];

    preB1(sbase, w1hi, w1lo, tid);   // fill during init barrier
    grid_sync();

    const float* sC = reinterpret_cast<const float*>(smem + CBASE);

    for (int t = 0; t < TT; ++t) {
        // ============ phase 1: z / r gates ============
        run_gemm1(smem, sbase,
                  &g_ha[0][p1_bm * HH], &g_ha[1][p1_bm * HH],
                  w1hi, w1lo, tid, grp, wm, wn);
        {
            const int er = tid >> 3;              // 0..63
            const int ecb = (tid & 7) << 3;       // 8 cols
            const float* cr = sC + er * LDMC + ecb;
            float v[8];
            {
                float4 a0 = *reinterpret_cast<const float4*>(cr);
                float4 a1 = *reinterpret_cast<const float4*>(cr + 4);
#pragma unroll
                for (int g = 1; g < 4; ++g) {
                    const float* crg = cr + g * (64 * LDMC);
                    float4 b0 = *reinterpret_cast<const float4*>(crg);
                    float4 b1 = *reinterpret_cast<const float4*>(crg + 4);
                    a0.x += b0.x; a0.y += b0.y; a0.z += b0.z; a0.w += b0.w;
                    a1.x += b1.x; a1.y += b1.y; a1.z += b1.z; a1.w += b1.w;
                }
                v[0] = a0.x; v[1] = a0.y; v[2] = a0.z; v[3] = a0.w;
                v[4] = a1.x; v[5] = a1.y; v[6] = a1.z; v[7] = a1.w;
            }
            const int b = p1_bm + er;
            const int tok = x[b * TT + t];
            const float* __restrict__ pre = &g_pre[p1_gate][tok][p1_jb + ecb];
            if (p1_gate == 0) {
                float* __restrict__ dst = &g_z[b * HH + p1_jb + ecb];
#pragma unroll
                for (int q = 0; q < 2; ++q) {
                    float4 p = *reinterpret_cast<const float4*>(pre + q * 4);
                    float4 o;
                    o.x = sigf(v[q * 4 + 0] + p.x);
                    o.y = sigf(v[q * 4 + 1] + p.y);
                    o.z = sigf(v[q * 4 + 2] + p.z);
                    o.w = sigf(v[q * 4 + 3] + p.w);
                    *reinterpret_cast<float4*>(dst + q * 4) = o;
                }
            } else {
                const float* __restrict__ hrow = &g_h[b * HH + p1_jb + ecb];
                float hr[8];
#pragma unroll
                for (int q = 0; q < 2; ++q) {
                    float4 p = *reinterpret_cast<const float4*>(pre + q * 4);
                    float4 h4 = *reinterpret_cast<const float4*>(hrow + q * 4);
                    hr[q * 4 + 0] = sigf(v[q * 4 + 0] + p.x) * h4.x;
                    hr[q * 4 + 1] = sigf(v[q * 4 + 1] + p.y) * h4.y;
                    hr[q * 4 + 2] = sigf(v[q * 4 + 2] + p.z) * h4.z;
                    hr[q * 4 + 3] = sigf(v[q * 4 + 3] + p.w) * h4.w;
                }
                uint32_t phi[4], plo[4];
#pragma unroll
                for (int q = 0; q < 4; ++q) {
                    float a = hr[2 * q], bx = hr[2 * q + 1];
                    float ea = a - __bfloat162float(__float2bfloat16(a));
                    float eb = bx - __bfloat162float(__float2bfloat16(bx));
                    phi[q] = pack_bf2(a, bx);
                    plo[q] = pack_bf2(ea, eb);
                }
                *reinterpret_cast<uint4*>(&g_hra[0][b * HH + p1_jb + ecb]) =
                    make_uint4(phi[0], phi[1], phi[2], phi[3]);
                *reinterpret_cast<uint4*>(&g_hra[1][b * HH + p1_jb + ecb]) =
                    make_uint4(plo[0], plo[1], plo[2], plo[3]);
            }
        }
        __syncthreads();                  // epilogue reads done before B overwrite
        preB2(sbase, w2hi, w2lo, tid);    // fill during barrier wait
        grid_sync();

        // ============ phase 2: candidate + state update ============
        run_gemm2(smem, sbase,
                  &g_hra[0][p2_bm * HH], &g_hra[1][p2_bm * HH],
                  w2hi, w2lo, tid, grp, wm, wn);
        {
            const int er = tid >> 4;              // 0..31
            const int ecb = (tid & 15) << 2;      // 4 cols
            const float* cr = sC + er * LDMC + ecb;
            float4 v = *reinterpret_cast<const float4*>(cr);
#pragma unroll
            for (int g = 1; g < 4; ++g) {
                float4 bq = *reinterpret_cast<const float4*>(cr + g * (32 * LDMC));
                v.x += bq.x; v.y += bq.y; v.z += bq.z; v.w += bq.w;
            }
            const int b = p2_bm + er;
            const int tok = x[b * TT + t];
            const float* __restrict__ pre = &g_pre[2][tok][p2_jb + ecb];
            float* __restrict__ hrow = &g_h[b * HH + p2_jb + ecb];
            const float* __restrict__ zrow = &g_z[b * HH + p2_jb + ecb];
            float4 p = *reinterpret_cast<const float4*>(pre);
            float4 h4 = *reinterpret_cast<const float4*>(hrow);
            float4 z4 = *reinterpret_cast<const float4*>(zrow);
            float hn[4];
            hn[0] = h4.x + z4.x * (fast_tanh(v.x + p.x) - h4.x);
            hn[1] = h4.y + z4.y * (fast_tanh(v.y + p.y) - h4.y);
            hn[2] = h4.z + z4.z * (fast_tanh(v.z + p.z) - h4.z);
            hn[3] = h4.w + z4.w * (fast_tanh(v.w + p.w) - h4.w);
            *reinterpret_cast<float4*>(hrow) = make_float4(hn[0], hn[1], hn[2], hn[3]);
            uint32_t phi[2], plo[2];
#pragma unroll
            for (int q = 0; q < 2; ++q) {
                float a = hn[2 * q], bx = hn[2 * q + 1];
                float ea = a - __bfloat162float(__float2bfloat16(a));
                float eb = bx - __bfloat162float(__float2bfloat16(bx));
                phi[q] = pack_bf2(a, bx);
                plo[q] = pack_bf2(ea, eb);
            }
            *reinterpret_cast<uint2*>(&g_ha[0][b * HH + p2_jb + ecb]) = make_uint2(phi[0], phi[1]);
            *reinterpret_cast<uint2*>(&g_ha[1][b * HH + p2_jb + ecb]) = make_uint2(plo[0], plo[1]);
        }
        __syncthreads();
        preB1(sbase, w1hi, w1lo, tid);    // for next t (harmless at t=TT-1)
        grid_sync();
    }

    // ============ output projection ============
    const int warpId = (cta << 4) + wid;
    const int nWarps = NCTA << 4;
    for (int oc = warpId; oc < BB * CC; oc += nWarps) {
        const int b = oc / CC;
        const int c = oc - b * CC;
        const float* hrow = &g_h[b * HH];
        const float* wrow = &Wph[c * HH];
        float s = 0.f;
        for (int j = lane; j < HH; j += 32)
            s += hrow[j] * wrow[j];
#pragma unroll
        for (int off = 16; off; off >>= 1)
            s += __shfl_xor_sync(0xffffffffu, s, off);
        if (lane == 0) out[oc] = s + bp[c];
    }
}

// ---------------- launch ----------------
extern "C" void kernel_launch(void* const* d_in, const int* in_sizes, int n_in,
                              void* d_out, int out_size) {
    const int*   x     = (const int*)d_in[0];
    const float* embed = (const float*)d_in[1];
    const float* Wz    = (const float*)d_in[2];
    const float* Wr    = (const float*)d_in[3];
    const float* Wc    = (const float*)d_in[4];
    const float* Wph   = (const float*)d_in[5];
    const float* bp    = (const float*)d_in[6];
    float* out = (float*)d_out;

    cudaFuncSetAttribute(gru_tc, cudaFuncAttributeMaxDynamicSharedMemorySize, SMEM_TOTAL);

    const long total = 3L * HH * HH + 3L * VV * HH;
    precompute_kernel<<<(unsigned)((total + 255) / 256), 256>>>(embed, Wz, Wr, Wc);
    gru_tc<<<NCTA, NTHR, SMEM_TOTAL>>>(x, Wph, bp, out);
}